// round 2
// baseline (speedup 1.0000x reference)
#include <cuda_runtime.h>

#define D 128
#define MAXN 50000
#define MAXE 800000

__device__ float g_fi[MAXN * D];
__device__ float g_fj[MAXN * D];
__device__ float g_a1[MAXN];
__device__ float g_a2[MAXN];
__device__ int   g_is64;

// ---------------------------------------------------------------------------
// Kernel 1: fused dual GEMM  fi = relu(X @ W1^T + b1), fj = relu(X @ W2^T + b2)
// blockIdx.y selects which weight matrix. Classic smem-tiled sgemm:
// BM=128, BN=128 (full D_OUT), BK=32, 256 threads, 8x8 register micro-tile.
// ---------------------------------------------------------------------------
#define BM 128
#define BN 128
#define BK 32

__global__ __launch_bounds__(256) void gemm_kernel(
    const float* __restrict__ A,
    const float* __restrict__ W1, const float* __restrict__ b1,
    const float* __restrict__ W2, const float* __restrict__ b2,
    int n)
{
    __shared__ __align__(16) float As[BK][BM + 4];
    __shared__ __align__(16) float Bs[BK][BN + 4];

    const float* W    = blockIdx.y ? W2 : W1;
    const float* bias = blockIdx.y ? b2 : b1;
    float*       out  = blockIdx.y ? g_fj : g_fi;

    const int tid = threadIdx.x;
    const int tx  = tid & 15;      // 0..15  -> output-dim blocks of 8
    const int ty  = tid >> 4;      // 0..15  -> node blocks of 8
    const int m0  = blockIdx.x * BM;

    float acc[8][8];
#pragma unroll
    for (int i = 0; i < 8; i++)
#pragma unroll
        for (int j = 0; j < 8; j++) acc[i][j] = 0.f;

    const int lm  = tid >> 1;           // 0..127 : row within tile for loading
    const int lk0 = (tid & 1) * 16;     // 0 or 16 : k sub-range

    for (int kt = 0; kt < D; kt += BK) {
        // Load A tile (transposed into As[k][m]) — guard node tail
#pragma unroll
        for (int v = 0; v < 4; v++) {
            int k = lk0 + v * 4;
            float4 av = make_float4(0.f, 0.f, 0.f, 0.f);
            if (m0 + lm < n)
                av = *(const float4*)(A + (size_t)(m0 + lm) * D + kt + k);
            As[k + 0][lm] = av.x; As[k + 1][lm] = av.y;
            As[k + 2][lm] = av.z; As[k + 3][lm] = av.w;
        }
        // Load B tile: W is [128][128] row-major; Bs[k][ndim] = W[ndim][kt+k]
#pragma unroll
        for (int v = 0; v < 4; v++) {
            int k = lk0 + v * 4;
            float4 bv = *(const float4*)(W + (size_t)lm * D + kt + k);
            Bs[k + 0][lm] = bv.x; Bs[k + 1][lm] = bv.y;
            Bs[k + 2][lm] = bv.z; Bs[k + 3][lm] = bv.w;
        }
        __syncthreads();

#pragma unroll
        for (int k = 0; k < BK; k++) {
            float a[8], b[8];
            *(float4*)&a[0] = *(const float4*)&As[k][ty * 8 + 0];
            *(float4*)&a[4] = *(const float4*)&As[k][ty * 8 + 4];
            *(float4*)&b[0] = *(const float4*)&Bs[k][tx * 8 + 0];
            *(float4*)&b[4] = *(const float4*)&Bs[k][tx * 8 + 4];
#pragma unroll
            for (int i = 0; i < 8; i++)
#pragma unroll
                for (int j = 0; j < 8; j++)
                    acc[i][j] += a[i] * b[j];
        }
        __syncthreads();
    }

    // Epilogue: bias + relu, store to fi/fj
#pragma unroll
    for (int i = 0; i < 8; i++) {
        int m = m0 + ty * 8 + i;
        if (m < n) {
#pragma unroll
            for (int j = 0; j < 8; j += 4) {
                int nd = tx * 8 + j;
                float4 r;
                r.x = fmaxf(acc[i][j + 0] + bias[nd + 0], 0.f);
                r.y = fmaxf(acc[i][j + 1] + bias[nd + 1], 0.f);
                r.z = fmaxf(acc[i][j + 2] + bias[nd + 2], 0.f);
                r.w = fmaxf(acc[i][j + 3] + bias[nd + 3], 0.f);
                *(float4*)(out + (size_t)m * D + nd) = r;
            }
        }
    }
}

// ---------------------------------------------------------------------------
// Kernel: detect edge_index dtype (int64 vs int32).
// For int64 little-endian, every odd 32-bit word (high half) is 0 since
// values < 50000. For int32, odd words are random indices.
// ---------------------------------------------------------------------------
__global__ void detect_kernel(const unsigned int* __restrict__ ei)
{
    int lane = threadIdx.x;  // 0..31, checks 64 candidate high-words
    unsigned v = ei[2 * lane + 1] | ei[2 * (lane + 32) + 1];
    unsigned all_zero = __all_sync(0xFFFFFFFFu, v == 0u);
    if (lane == 0) g_is64 = (int)all_zero;
}

// ---------------------------------------------------------------------------
// Kernel 2: per-node — a1/a2 attention logits + self-loop initialization:
//   out[n] = fi[n] + sigmoid(a1[n]+a2[n]) * fj[n]
// One warp per node; lane l owns dims [4l, 4l+4).
// ---------------------------------------------------------------------------
__global__ __launch_bounds__(256) void node_kernel(
    const float* __restrict__ wa1, const float* __restrict__ ba1,
    const float* __restrict__ wa2, const float* __restrict__ ba2,
    float* __restrict__ out, int n)
{
    int warp = (blockIdx.x * blockDim.x + threadIdx.x) >> 5;
    int lane = threadIdx.x & 31;
    if (warp >= n) return;

    float4 fi4 = *(const float4*)(g_fi + (size_t)warp * D + lane * 4);
    float4 fj4 = *(const float4*)(g_fj + (size_t)warp * D + lane * 4);
    float4 w1  = *(const float4*)(wa1 + lane * 4);
    float4 w2  = *(const float4*)(wa2 + lane * 4);

    float s1 = fi4.x * w1.x + fi4.y * w1.y + fi4.z * w1.z + fi4.w * w1.w;
    float s2 = fj4.x * w2.x + fj4.y * w2.y + fj4.z * w2.z + fj4.w * w2.w;
#pragma unroll
    for (int off = 16; off >= 1; off >>= 1) {
        s1 += __shfl_xor_sync(0xFFFFFFFFu, s1, off);
        s2 += __shfl_xor_sync(0xFFFFFFFFu, s2, off);
    }
    float a1v = s1 + ba1[0];
    float a2v = s2 + ba2[0];
    if (lane == 0) { g_a1[warp] = a1v; g_a2[warp] = a2v; }

    float sg = 1.f / (1.f + __expf(-(a1v + a2v)));
    float4 o;
    o.x = fi4.x + sg * fj4.x;
    o.y = fi4.y + sg * fj4.y;
    o.z = fi4.z + sg * fj4.z;
    o.w = fi4.w + sg * fj4.w;
    *(float4*)(out + (size_t)warp * D + lane * 4) = o;
}

// ---------------------------------------------------------------------------
// Kernel 3: edge scatter. One warp per edge:
//   att = sigmoid(a1[row] + a2[col]);  out[row] += att * fj[col]
// Lane l handles a float4 slice; scatter via vectorized red.global.add.v4.f32.
// ---------------------------------------------------------------------------
__global__ __launch_bounds__(256) void edge_kernel(
    const void* __restrict__ ei, float* __restrict__ out, int e)
{
    int warp = (blockIdx.x * blockDim.x + threadIdx.x) >> 5;
    int lane = threadIdx.x & 31;
    if (warp >= e) return;

    int r, c;
    if (g_is64) {
        const long long* p = (const long long*)ei;
        r = (int)p[warp];
        c = (int)p[(size_t)e + warp];
    } else {
        const int* p = (const int*)ei;
        r = p[warp];
        c = p[(size_t)e + warp];
    }

    float att = 1.f / (1.f + __expf(-(g_a1[r] + g_a2[c])));
    float4 v = *(const float4*)(g_fj + (size_t)c * D + lane * 4);
    float* dst = out + (size_t)r * D + lane * 4;
    asm volatile(
        "red.global.add.v4.f32 [%0], {%1, %2, %3, %4};"
        :: "l"(dst), "f"(att * v.x), "f"(att * v.y),
           "f"(att * v.z), "f"(att * v.w)
        : "memory");
}

// ---------------------------------------------------------------------------
extern "C" void kernel_launch(void* const* d_in, const int* in_sizes, int n_in,
                              void* d_out, int out_size)
{
    const float* feat = (const float*)d_in[0];
    const float* W1   = (const float*)d_in[1];
    const float* b1   = (const float*)d_in[2];
    const float* W2   = (const float*)d_in[3];
    const float* b2   = (const float*)d_in[4];
    const float* wa1  = (const float*)d_in[5];
    const float* ba1  = (const float*)d_in[6];
    const float* wa2  = (const float*)d_in[7];
    const float* ba2  = (const float*)d_in[8];
    const void*  ei   = d_in[9];

    int n = in_sizes[0] / D;
    int e = in_sizes[9] / 2;
    float* out = (float*)d_out;

    dim3 grid_g((n + BM - 1) / BM, 2);
    gemm_kernel<<<grid_g, 256>>>(feat, W1, b1, W2, b2, n);

    detect_kernel<<<1, 32>>>((const unsigned int*)ei);

    node_kernel<<<(n + 7) / 8, 256>>>(wa1, ba1, wa2, ba2, out, n);

    edge_kernel<<<(e + 7) / 8, 256>>>(ei, out, e);
}

// round 3
// speedup vs baseline: 1.3162x; 1.3162x over previous
#include <cuda_runtime.h>

#define D 128
#define MAXN 50000
#define MAXE 800000

__device__ float g_fi[MAXN * D];
__device__ float g_fj[MAXN * D];
__device__ float g_a1[MAXN];
__device__ float g_a2[MAXN];
__device__ int   g_is64;
__device__ int   g_cnt[MAXN];        // per-row degree (histogram)
__device__ int   g_rowptr[MAXN + 1]; // CSR row pointers
__device__ int   g_cursor[MAXN];     // fill cursors
__device__ int   g_csr_col[MAXE];    // CSR column (source node) list

// ---------------------------------------------------------------------------
// Kernel 1: fused dual GEMM  fi = relu(X @ W1^T + b1), fj = relu(X @ W2^T + b2)
// blockIdx.y selects which weight matrix. BM=128, BN=128 (full D_OUT), BK=32,
// 256 threads, 8x8 register micro-tile. Epilogue also computes the attention
// logits a1/a2 = relu_out @ wa + ba via a 16-lane shfl reduction (each block
// holds complete 128-dim output rows).
// ---------------------------------------------------------------------------
#define BM 128
#define BN 128
#define BK 32

__global__ __launch_bounds__(256) void gemm_kernel(
    const float* __restrict__ A,
    const float* __restrict__ W1, const float* __restrict__ b1,
    const float* __restrict__ W2, const float* __restrict__ b2,
    const float* __restrict__ wa1, const float* __restrict__ ba1,
    const float* __restrict__ wa2, const float* __restrict__ ba2,
    int n)
{
    __shared__ __align__(16) float As[BK][BM + 4];
    __shared__ __align__(16) float Bs[BK][BN + 4];

    const float* W    = blockIdx.y ? W2  : W1;
    const float* bias = blockIdx.y ? b2  : b1;
    const float* wa   = blockIdx.y ? wa2 : wa1;
    const float* bap  = blockIdx.y ? ba2 : ba1;
    float*       out  = blockIdx.y ? g_fj : g_fi;
    float*       aout = blockIdx.y ? g_a2 : g_a1;

    const int tid = threadIdx.x;
    const int tx  = tid & 15;      // 0..15  -> output-dim blocks of 8
    const int ty  = tid >> 4;      // 0..15  -> node blocks of 8
    const int m0  = blockIdx.x * BM;

    float acc[8][8];
#pragma unroll
    for (int i = 0; i < 8; i++)
#pragma unroll
        for (int j = 0; j < 8; j++) acc[i][j] = 0.f;

    const int lm  = tid >> 1;           // 0..127 : row within tile for loading
    const int lk0 = (tid & 1) * 16;     // 0 or 16 : k sub-range

    for (int kt = 0; kt < D; kt += BK) {
#pragma unroll
        for (int v = 0; v < 4; v++) {
            int k = lk0 + v * 4;
            float4 av = make_float4(0.f, 0.f, 0.f, 0.f);
            if (m0 + lm < n)
                av = *(const float4*)(A + (size_t)(m0 + lm) * D + kt + k);
            As[k + 0][lm] = av.x; As[k + 1][lm] = av.y;
            As[k + 2][lm] = av.z; As[k + 3][lm] = av.w;
        }
#pragma unroll
        for (int v = 0; v < 4; v++) {
            int k = lk0 + v * 4;
            float4 bv = *(const float4*)(W + (size_t)lm * D + kt + k);
            Bs[k + 0][lm] = bv.x; Bs[k + 1][lm] = bv.y;
            Bs[k + 2][lm] = bv.z; Bs[k + 3][lm] = bv.w;
        }
        __syncthreads();

#pragma unroll
        for (int k = 0; k < BK; k++) {
            float a[8], b[8];
            *(float4*)&a[0] = *(const float4*)&As[k][ty * 8 + 0];
            *(float4*)&a[4] = *(const float4*)&As[k][ty * 8 + 4];
            *(float4*)&b[0] = *(const float4*)&Bs[k][tx * 8 + 0];
            *(float4*)&b[4] = *(const float4*)&Bs[k][tx * 8 + 4];
#pragma unroll
            for (int i = 0; i < 8; i++)
#pragma unroll
                for (int j = 0; j < 8; j++)
                    acc[i][j] += a[i] * b[j];
        }
        __syncthreads();
    }

    // Epilogue: bias + relu, store fi/fj, and attention logit dot
    float wl[8];
#pragma unroll
    for (int j = 0; j < 8; j += 4)
        *(float4*)&wl[j] = *(const float4*)(wa + tx * 8 + j);
    float ba0 = bap[0];

#pragma unroll
    for (int i = 0; i < 8; i++) {
        int m = m0 + ty * 8 + i;
        float r[8];
#pragma unroll
        for (int j = 0; j < 8; j++)
            r[j] = fmaxf(acc[i][j] + bias[tx * 8 + j], 0.f);
        if (m < n) {
            *(float4*)(out + (size_t)m * D + tx * 8 + 0) = *(float4*)&r[0];
            *(float4*)(out + (size_t)m * D + tx * 8 + 4) = *(float4*)&r[4];
        }
        float dot = 0.f;
#pragma unroll
        for (int j = 0; j < 8; j++) dot += r[j] * wl[j];
        // reduce across the 16 tx lanes (offsets 1,2,4,8 stay in 16-lane halves)
#pragma unroll
        for (int off = 1; off < 16; off <<= 1)
            dot += __shfl_xor_sync(0xFFFFFFFFu, dot, off);
        if (tx == 0 && m < n) aout[m] = dot + ba0;
    }
}

// ---------------------------------------------------------------------------
// Detect edge_index dtype (int64 vs int32): int64 values < 50000 have all
// high 32-bit words zero.
// ---------------------------------------------------------------------------
__global__ void detect_kernel(const unsigned int* __restrict__ ei)
{
    int lane = threadIdx.x;
    unsigned v = ei[2 * lane + 1] | ei[2 * (lane + 32) + 1];
    unsigned all_zero = __all_sync(0xFFFFFFFFu, v == 0u);
    if (lane == 0) g_is64 = (int)all_zero;
}

__device__ __forceinline__ int load_idx(const void* ei, size_t pos)
{
    if (g_is64) return (int)((const long long*)ei)[pos];
    return ((const int*)ei)[pos];
}

// ---------------------------------------------------------------------------
// CSR construction: zero counts -> histogram rows -> exclusive scan -> fill
// ---------------------------------------------------------------------------
__global__ void zero_kernel(int n)
{
    int i = blockIdx.x * blockDim.x + threadIdx.x;
    if (i < n) g_cnt[i] = 0;
}

__global__ __launch_bounds__(256) void hist_kernel(const void* __restrict__ ei, int e)
{
    int i = blockIdx.x * blockDim.x + threadIdx.x;
    if (i >= e) return;
    int r = load_idx(ei, i);
    atomicAdd(&g_cnt[r], 1);
}

#define SCAN_T 1024
__global__ __launch_bounds__(SCAN_T) void scan_kernel(int n)
{
    __shared__ int sm[SCAN_T];
    int t = threadIdx.x;
    int per = (n + SCAN_T - 1) / SCAN_T;
    int base = t * per;
    int s = 0;
    for (int i = 0; i < per; i++) {
        int idx = base + i;
        if (idx < n) s += g_cnt[idx];
    }
    sm[t] = s;
    __syncthreads();
    // inclusive Hillis-Steele scan over chunk sums
    for (int off = 1; off < SCAN_T; off <<= 1) {
        int y = (t >= off) ? sm[t - off] : 0;
        __syncthreads();
        if (t >= off) sm[t] += y;
        __syncthreads();
    }
    int run = sm[t] - s;  // exclusive prefix for this chunk
    for (int i = 0; i < per; i++) {
        int idx = base + i;
        if (idx < n) {
            int c = g_cnt[idx];
            g_rowptr[idx] = run;
            g_cursor[idx] = run;
            run += c;
        }
    }
    if (t == SCAN_T - 1) g_rowptr[n] = run;
}

__global__ __launch_bounds__(256) void fill_kernel(const void* __restrict__ ei, int e)
{
    int i = blockIdx.x * blockDim.x + threadIdx.x;
    if (i >= e) return;
    int r = load_idx(ei, i);
    int c = load_idx(ei, (size_t)e + i);
    int pos = atomicAdd(&g_cursor[r], 1);
    g_csr_col[pos] = c;
}

// ---------------------------------------------------------------------------
// Gather: one warp per destination node. Accumulate self-loop + all incoming
// edges in registers, then a single non-atomic store. No atomics, no out read.
// ---------------------------------------------------------------------------
__global__ __launch_bounds__(256) void gather_kernel(float* __restrict__ out, int n)
{
    int w    = (blockIdx.x * blockDim.x + threadIdx.x) >> 5;
    int lane = threadIdx.x & 31;
    if (w >= n) return;

    float a1v = g_a1[w];

    // self loop
    float att = 1.f / (1.f + __expf(-(a1v + g_a2[w])));
    float4 fi4 = *(const float4*)(g_fi + (size_t)w * D + lane * 4);
    float4 fj4 = *(const float4*)(g_fj + (size_t)w * D + lane * 4);
    float4 acc;
    acc.x = fi4.x + att * fj4.x;
    acc.y = fi4.y + att * fj4.y;
    acc.z = fi4.z + att * fj4.z;
    acc.w = fi4.w + att * fj4.w;

    int s = g_rowptr[w];
    int t = g_rowptr[w + 1];
    for (int k = s; k < t; k++) {
        int c = __ldg(&g_csr_col[k]);
        float a = 1.f / (1.f + __expf(-(a1v + __ldg(&g_a2[c]))));
        float4 v = *(const float4*)(g_fj + (size_t)c * D + lane * 4);
        acc.x += a * v.x;
        acc.y += a * v.y;
        acc.z += a * v.z;
        acc.w += a * v.w;
    }
    *(float4*)(out + (size_t)w * D + lane * 4) = acc;
}

// ---------------------------------------------------------------------------
extern "C" void kernel_launch(void* const* d_in, const int* in_sizes, int n_in,
                              void* d_out, int out_size)
{
    const float* feat = (const float*)d_in[0];
    const float* W1   = (const float*)d_in[1];
    const float* b1   = (const float*)d_in[2];
    const float* W2   = (const float*)d_in[3];
    const float* b2   = (const float*)d_in[4];
    const float* wa1  = (const float*)d_in[5];
    const float* ba1  = (const float*)d_in[6];
    const float* wa2  = (const float*)d_in[7];
    const float* ba2  = (const float*)d_in[8];
    const void*  ei   = d_in[9];

    int n = in_sizes[0] / D;
    int e = in_sizes[9] / 2;
    float* out = (float*)d_out;

    detect_kernel<<<1, 32>>>((const unsigned int*)ei);

    dim3 grid_g((n + BM - 1) / BM, 2);
    gemm_kernel<<<grid_g, 256>>>(feat, W1, b1, W2, b2, wa1, ba1, wa2, ba2, n);

    zero_kernel<<<(n + 255) / 256, 256>>>(n);
    hist_kernel<<<(e + 255) / 256, 256>>>(ei, e);
    scan_kernel<<<1, SCAN_T>>>(n);
    fill_kernel<<<(e + 255) / 256, 256>>>(ei, e);

    gather_kernel<<<(n + 7) / 8, 256>>>(out, n);
}

// round 4
// speedup vs baseline: 1.4937x; 1.1348x over previous
#include <cuda_runtime.h>
#include <cstdint>

#define D 128
#define MAXN 50000
#define MAXE 800000

__device__ float g_fi[MAXN * D];
__device__ float g_fj[MAXN * D];
__device__ float g_a1[MAXN];
__device__ float g_a2[MAXN];
__device__ int   g_is64;
__device__ int   g_cnt[MAXN];
__device__ int   g_rowptr[MAXN + 1];
__device__ int   g_cursor[MAXN];
__device__ int   g_csr_col[MAXE];

// ---------------------------------------------------------------------------
// TF32 helpers: 3xTF32 split  x = hi + lo, hi = round_tf32(x)
// ---------------------------------------------------------------------------
__device__ __forceinline__ uint32_t f2tf32(float x)
{
    uint32_t r;
    asm("cvt.rna.tf32.f32 %0, %1;" : "=r"(r) : "f"(x));
    return r;
}

__device__ __forceinline__ void mma_tf32(float* c, const uint32_t* a,
                                         const uint32_t* b)
{
    asm volatile(
        "mma.sync.aligned.m16n8k8.row.col.f32.tf32.tf32.f32 "
        "{%0,%1,%2,%3}, {%4,%5,%6,%7}, {%8,%9}, {%0,%1,%2,%3};"
        : "+f"(c[0]), "+f"(c[1]), "+f"(c[2]), "+f"(c[3])
        : "r"(a[0]), "r"(a[1]), "r"(a[2]), "r"(a[3]), "r"(b[0]), "r"(b[1]));
}

// ---------------------------------------------------------------------------
// Kernel 1: dual GEMM on tensor cores (3xTF32).
//   fi/fj = relu(X @ W^T + b);  a1/a2 = relu_out @ wa + ba  (fused epilogue)
// BM=128 rows/block, full N=128, BK=32. 8 warps; warp w owns rows
// [w*16, w*16+16) x all 128 cols => 16 n-tiles of m16n8k8, 2 k8-steps... (4 per BK)
// smem holds hi/lo split tiles of X and W.
// ---------------------------------------------------------------------------
#define BM 128
#define BK 32
#define SROW 36                    // 32 + 4 pad (conflict-free: stride%32==4)
#define STILE (BM * SROW)

__global__ __launch_bounds__(256, 2) void gemm_tf32_kernel(
    const float* __restrict__ A,
    const float* __restrict__ W1, const float* __restrict__ b1,
    const float* __restrict__ W2, const float* __restrict__ b2,
    const float* __restrict__ wa1, const float* __restrict__ ba1,
    const float* __restrict__ wa2, const float* __restrict__ ba2,
    int n)
{
    extern __shared__ float smem_f[];
    float* sAhi = smem_f;
    float* sAlo = smem_f + STILE;
    float* sWhi = smem_f + 2 * STILE;
    float* sWlo = smem_f + 3 * STILE;

    const float* W    = blockIdx.y ? W2  : W1;
    const float* bias = blockIdx.y ? b2  : b1;
    const float* wa   = blockIdx.y ? wa2 : wa1;
    const float* bap  = blockIdx.y ? ba2 : ba1;
    float*       out  = blockIdx.y ? g_fj : g_fi;
    float*       aout = blockIdx.y ? g_a2 : g_a1;

    const int tid  = threadIdx.x;
    const int warp = tid >> 5;
    const int lane = tid & 31;
    const int q    = lane & 3;   // threadID_in_group (k / col-pair index)
    const int g    = lane >> 2;  // groupID (row / n index)
    const int m0   = blockIdx.x * BM;

    float acc[16][4];            // 16 n-tiles (n = tn*8), 4 accum regs each
#pragma unroll
    for (int t = 0; t < 16; t++)
#pragma unroll
        for (int j = 0; j < 4; j++) acc[t][j] = 0.f;

    const int lr  = tid >> 1;          // 0..127 row within tile
    const int lk0 = (tid & 1) * 16;    // 0 or 16

#pragma unroll 1
    for (int kt = 0; kt < D; kt += BK) {
        // Global -> smem with hi/lo tf32 split
#pragma unroll
        for (int v = 0; v < 4; v++) {
            int k = lk0 + v * 4;
            float4 av = make_float4(0.f, 0.f, 0.f, 0.f);
            if (m0 + lr < n)
                av = *(const float4*)(A + (size_t)(m0 + lr) * D + kt + k);
            float4 ah, al;
            ah.x = __uint_as_float(f2tf32(av.x)); al.x = av.x - ah.x;
            ah.y = __uint_as_float(f2tf32(av.y)); al.y = av.y - ah.y;
            ah.z = __uint_as_float(f2tf32(av.z)); al.z = av.z - ah.z;
            ah.w = __uint_as_float(f2tf32(av.w)); al.w = av.w - ah.w;
            *(float4*)(sAhi + lr * SROW + k) = ah;
            *(float4*)(sAlo + lr * SROW + k) = al;

            float4 wv = *(const float4*)(W + (size_t)lr * D + kt + k);
            float4 wh, wl;
            wh.x = __uint_as_float(f2tf32(wv.x)); wl.x = wv.x - wh.x;
            wh.y = __uint_as_float(f2tf32(wv.y)); wl.y = wv.y - wh.y;
            wh.z = __uint_as_float(f2tf32(wv.z)); wl.z = wv.z - wh.z;
            wh.w = __uint_as_float(f2tf32(wv.w)); wl.w = wv.w - wh.w;
            *(float4*)(sWhi + lr * SROW + k) = wh;
            *(float4*)(sWlo + lr * SROW + k) = wl;
        }
        __syncthreads();

#pragma unroll
        for (int k8 = 0; k8 < BK; k8 += 8) {
            const int ar = (warp * 16 + g) * SROW + k8 + q;
            uint32_t ah[4], al[4];
            ah[0] = __float_as_uint(sAhi[ar]);
            ah[1] = __float_as_uint(sAhi[ar + 8 * SROW]);
            ah[2] = __float_as_uint(sAhi[ar + 4]);
            ah[3] = __float_as_uint(sAhi[ar + 8 * SROW + 4]);
            al[0] = __float_as_uint(sAlo[ar]);
            al[1] = __float_as_uint(sAlo[ar + 8 * SROW]);
            al[2] = __float_as_uint(sAlo[ar + 4]);
            al[3] = __float_as_uint(sAlo[ar + 8 * SROW + 4]);

#pragma unroll
            for (int tn = 0; tn < 16; tn++) {
                const int br = (tn * 8 + g) * SROW + k8 + q;
                uint32_t bh[2], bl[2];
                bh[0] = __float_as_uint(sWhi[br]);
                bh[1] = __float_as_uint(sWhi[br + 4]);
                bl[0] = __float_as_uint(sWlo[br]);
                bl[1] = __float_as_uint(sWlo[br + 4]);
                mma_tf32(acc[tn], ah, bh);
                mma_tf32(acc[tn], ah, bl);
                mma_tf32(acc[tn], al, bh);
            }
        }
        __syncthreads();
    }

    // Epilogue: bias + relu, store, fused attention-logit dot per row.
    // Thread owns rows m_lo = m0+warp*16+g and m_hi = m_lo+8;
    // cols tn*8 + 2q, +1 for tn in [0,16) -> warp covers all 128 cols.
    const int m_lo = m0 + warp * 16 + g;
    const int m_hi = m_lo + 8;
    float dot_lo = 0.f, dot_hi = 0.f;

#pragma unroll
    for (int tn = 0; tn < 16; tn++) {
        int c0 = tn * 8 + 2 * q;
        float bx = __ldg(bias + c0), by = __ldg(bias + c0 + 1);
        float wx = __ldg(wa + c0),   wy = __ldg(wa + c0 + 1);

        float r0 = fmaxf(acc[tn][0] + bx, 0.f);
        float r1 = fmaxf(acc[tn][1] + by, 0.f);
        float r2 = fmaxf(acc[tn][2] + bx, 0.f);
        float r3 = fmaxf(acc[tn][3] + by, 0.f);
        dot_lo += r0 * wx + r1 * wy;
        dot_hi += r2 * wx + r3 * wy;

        if (m_lo < n) *(float2*)(out + (size_t)m_lo * D + c0) = make_float2(r0, r1);
        if (m_hi < n) *(float2*)(out + (size_t)m_hi * D + c0) = make_float2(r2, r3);
    }
    // reduce over the 4 lanes of the quad (same g, q = 0..3)
#pragma unroll
    for (int off = 1; off < 4; off <<= 1) {
        dot_lo += __shfl_xor_sync(0xFFFFFFFFu, dot_lo, off);
        dot_hi += __shfl_xor_sync(0xFFFFFFFFu, dot_hi, off);
    }
    if (q == 0) {
        float ba0 = __ldg(bap);
        if (m_lo < n) aout[m_lo] = dot_lo + ba0;
        if (m_hi < n) aout[m_hi] = dot_hi + ba0;
    }
}

// ---------------------------------------------------------------------------
// Detect edge_index dtype (int64 vs int32).
// ---------------------------------------------------------------------------
__global__ void detect_kernel(const unsigned int* __restrict__ ei)
{
    int lane = threadIdx.x;
    unsigned v = ei[2 * lane + 1] | ei[2 * (lane + 32) + 1];
    unsigned all_zero = __all_sync(0xFFFFFFFFu, v == 0u);
    if (lane == 0) g_is64 = (int)all_zero;
}

__device__ __forceinline__ int load_idx(const void* ei, size_t pos)
{
    if (g_is64) return (int)((const long long*)ei)[pos];
    return ((const int*)ei)[pos];
}

// ---------------------------------------------------------------------------
// CSR construction: zero -> histogram -> scan -> fill
// ---------------------------------------------------------------------------
__global__ void zero_kernel(int n)
{
    int i = blockIdx.x * blockDim.x + threadIdx.x;
    if (i < n) g_cnt[i] = 0;
}

__global__ __launch_bounds__(256) void hist_kernel(const void* __restrict__ ei, int e)
{
    int i = blockIdx.x * blockDim.x + threadIdx.x;
    if (i >= e) return;
    int r = load_idx(ei, i);
    atomicAdd(&g_cnt[r], 1);
}

#define SCAN_T 1024
__global__ __launch_bounds__(SCAN_T) void scan_kernel(int n)
{
    __shared__ int sm[SCAN_T];
    int t = threadIdx.x;
    int per = (n + SCAN_T - 1) / SCAN_T;
    int base = t * per;
    int s = 0;
    for (int i = 0; i < per; i++) {
        int idx = base + i;
        if (idx < n) s += g_cnt[idx];
    }
    sm[t] = s;
    __syncthreads();
    for (int off = 1; off < SCAN_T; off <<= 1) {
        int y = (t >= off) ? sm[t - off] : 0;
        __syncthreads();
        if (t >= off) sm[t] += y;
        __syncthreads();
    }
    int run = sm[t] - s;
    for (int i = 0; i < per; i++) {
        int idx = base + i;
        if (idx < n) {
            int c = g_cnt[idx];
            g_rowptr[idx] = run;
            g_cursor[idx] = run;
            run += c;
        }
    }
    if (t == SCAN_T - 1) g_rowptr[n] = run;
}

__global__ __launch_bounds__(256) void fill_kernel(const void* __restrict__ ei, int e)
{
    int i = blockIdx.x * blockDim.x + threadIdx.x;
    if (i >= e) return;
    int r = load_idx(ei, i);
    int c = load_idx(ei, (size_t)e + i);
    int pos = atomicAdd(&g_cursor[r], 1);
    g_csr_col[pos] = c;
}

// ---------------------------------------------------------------------------
// Gather: one warp per destination node; register accumulation, single store.
// ---------------------------------------------------------------------------
__global__ __launch_bounds__(256) void gather_kernel(float* __restrict__ out, int n)
{
    int w    = (blockIdx.x * blockDim.x + threadIdx.x) >> 5;
    int lane = threadIdx.x & 31;
    if (w >= n) return;

    float a1v = g_a1[w];

    float att = 1.f / (1.f + __expf(-(a1v + g_a2[w])));
    float4 fi4 = *(const float4*)(g_fi + (size_t)w * D + lane * 4);
    float4 fj4 = *(const float4*)(g_fj + (size_t)w * D + lane * 4);
    float4 acc;
    acc.x = fi4.x + att * fj4.x;
    acc.y = fi4.y + att * fj4.y;
    acc.z = fi4.z + att * fj4.z;
    acc.w = fi4.w + att * fj4.w;

    int s = g_rowptr[w];
    int t = g_rowptr[w + 1];
    for (int k = s; k < t; k++) {
        int c = __ldg(&g_csr_col[k]);
        float a = 1.f / (1.f + __expf(-(a1v + __ldg(&g_a2[c]))));
        float4 v = *(const float4*)(g_fj + (size_t)c * D + lane * 4);
        acc.x += a * v.x;
        acc.y += a * v.y;
        acc.z += a * v.z;
        acc.w += a * v.w;
    }
    *(float4*)(out + (size_t)w * D + lane * 4) = acc;
}

// ---------------------------------------------------------------------------
extern "C" void kernel_launch(void* const* d_in, const int* in_sizes, int n_in,
                              void* d_out, int out_size)
{
    const float* feat = (const float*)d_in[0];
    const float* W1   = (const float*)d_in[1];
    const float* b1   = (const float*)d_in[2];
    const float* W2   = (const float*)d_in[3];
    const float* b2   = (const float*)d_in[4];
    const float* wa1  = (const float*)d_in[5];
    const float* ba1  = (const float*)d_in[6];
    const float* wa2  = (const float*)d_in[7];
    const float* ba2  = (const float*)d_in[8];
    const void*  ei   = d_in[9];

    int n = in_sizes[0] / D;
    int e = in_sizes[9] / 2;
    float* out = (float*)d_out;

    const int smem_bytes = 4 * STILE * sizeof(float);  // 73728
    cudaFuncSetAttribute(gemm_tf32_kernel,
                         cudaFuncAttributeMaxDynamicSharedMemorySize, smem_bytes);

    detect_kernel<<<1, 32>>>((const unsigned int*)ei);
    zero_kernel<<<(n + 255) / 256, 256>>>(n);

    dim3 grid_g((n + BM - 1) / BM, 2);
    gemm_tf32_kernel<<<grid_g, 256, smem_bytes>>>(feat, W1, b1, W2, b2,
                                                  wa1, ba1, wa2, ba2, n);

    hist_kernel<<<(e + 255) / 256, 256>>>(ei, e);
    scan_kernel<<<1, SCAN_T>>>(n);
    fill_kernel<<<(e + 255) / 256, 256>>>(ei, e);

    gather_kernel<<<(n + 7) / 8, 256>>>(out, n);
}

// round 7
// speedup vs baseline: 1.9365x; 1.2965x over previous
#include <cuda_runtime.h>
#include <cstdint>

#define D 128
#define MAXN 50000
#define MAXE 800000

__device__ float g_fi[MAXN * D];
__device__ float g_fj[MAXN * D];
__device__ float g_a1[MAXN];
__device__ float g_a2[MAXN];
__device__ int   g_is64;
__device__ int   g_cnt[MAXN];
__device__ int   g_rowptr[MAXN + 1];
__device__ int   g_cursor[MAXN];
__device__ int   g_csr_col[MAXE];

// ---------------------------------------------------------------------------
// TF32 helpers: 3xTF32 split  x = hi + lo, hi = round_tf32(x)
// ---------------------------------------------------------------------------
__device__ __forceinline__ float f2tf32(float x)
{
    uint32_t r;
    asm("cvt.rna.tf32.f32 %0, %1;" : "=r"(r) : "f"(x));
    return __uint_as_float(r);
}

__device__ __forceinline__ void mma_tf32(float* c, const uint32_t* a,
                                         const uint32_t* b)
{
    asm volatile(
        "mma.sync.aligned.m16n8k8.row.col.f32.tf32.tf32.f32 "
        "{%0,%1,%2,%3}, {%4,%5,%6,%7}, {%8,%9}, {%0,%1,%2,%3};"
        : "+f"(c[0]), "+f"(c[1]), "+f"(c[2]), "+f"(c[3])
        : "r"(a[0]), "r"(a[1]), "r"(a[2]), "r"(a[3]), "r"(b[0]), "r"(b[1]));
}

__device__ __forceinline__ void sts_split(float* hi, float* lo, int off, float4 v)
{
    float4 h, l;
    h.x = f2tf32(v.x); l.x = v.x - h.x;
    h.y = f2tf32(v.y); l.y = v.y - h.y;
    h.z = f2tf32(v.z); l.z = v.z - h.z;
    h.w = f2tf32(v.w); l.w = v.w - h.w;
    *(float4*)(hi + off) = h;
    *(float4*)(lo + off) = l;
}

// ---------------------------------------------------------------------------
// Kernel 1: dual GEMM on tensor cores (3xTF32), 512 threads / block.
// Whole W (hi/lo split) staged in smem once; A tiles (BK=32) double-buffered
// with register prefetch. 16 warps: warp w = (mw = w&7, nw = w>>3) owns rows
// [mw*16,+16) x cols [nw*64,+64)  (8 n-tiles of m16n8k8 -> acc[8][4]).
// Epilogue: bias+relu store + partial attention dot -> atomicAdd into a1/a2
// (pre-seeded with ba by init_kernel).
// ---------------------------------------------------------------------------
#define BM 128
#define BK 32
#define SRA 36                    // 32 + 4 pad
#define SRW 132                   // 128 + 4 pad
#define ATILE (BM * SRA)          // 4608 floats per (stage,half)
#define WTILE (BM * SRW)          // 16896 floats per half
#define GEMM_SMEM ((2 * WTILE + 4 * ATILE) * 4)   // 208896 bytes

__global__ __launch_bounds__(512) void gemm_tf32_kernel(
    const float* __restrict__ A,
    const float* __restrict__ W1, const float* __restrict__ b1,
    const float* __restrict__ W2, const float* __restrict__ b2,
    const float* __restrict__ wa1,
    const float* __restrict__ wa2,
    int n)
{
    extern __shared__ float sm[];
    float* sWhi = sm;
    float* sWlo = sm + WTILE;
    float* sA   = sm + 2 * WTILE;   // [stage][hi/lo][ATILE]

    const float* W    = blockIdx.y ? W2  : W1;
    const float* bias = blockIdx.y ? b2  : b1;
    const float* wa   = blockIdx.y ? wa2 : wa1;
    float*       out  = blockIdx.y ? g_fj : g_fi;
    float*       aout = blockIdx.y ? g_a2 : g_a1;

    const int tid  = threadIdx.x;
    const int warp = tid >> 5;
    const int lane = tid & 31;
    const int q    = lane & 3;
    const int g    = lane >> 2;
    const int mw   = warp & 7;
    const int nw   = warp >> 3;
    const int m0   = blockIdx.x * BM;

    // ---- stage whole W with hi/lo split (128x128, 8 float4 per thread) ----
#pragma unroll
    for (int i = 0; i < 8; i++) {
        int slot = tid + i * 512;          // 0..4095
        int row  = slot >> 5;              // 0..127
        int kv   = (slot & 31) * 4;        // 0..124
        float4 wv = *(const float4*)(W + (size_t)row * D + kv);
        sts_split(sWhi, sWlo, row * SRW + kv, wv);
    }

    // ---- A loader geometry: thread owns slots tid and tid+512 ----
    const int ar0 = tid >> 3;              // 0..63
    const int akv = (tid & 7) * 4;         // 0..28
    // rows ar0 and ar0+64

    // prologue: stage 0
    {
        float4 p0 = make_float4(0.f, 0.f, 0.f, 0.f);
        float4 p1 = make_float4(0.f, 0.f, 0.f, 0.f);
        if (m0 + ar0 < n)       p0 = *(const float4*)(A + (size_t)(m0 + ar0) * D + akv);
        if (m0 + ar0 + 64 < n)  p1 = *(const float4*)(A + (size_t)(m0 + ar0 + 64) * D + akv);
        sts_split(sA, sA + ATILE, ar0 * SRA + akv, p0);
        sts_split(sA, sA + ATILE, (ar0 + 64) * SRA + akv, p1);
    }
    __syncthreads();

    float acc[8][4];
#pragma unroll
    for (int t = 0; t < 8; t++)
#pragma unroll
        for (int j = 0; j < 4; j++) acc[t][j] = 0.f;

#pragma unroll
    for (int kt = 0; kt < 4; kt++) {
        // prefetch next A tile into registers
        float4 p0 = make_float4(0.f, 0.f, 0.f, 0.f);
        float4 p1 = make_float4(0.f, 0.f, 0.f, 0.f);
        if (kt < 3) {
            int kg = (kt + 1) * BK + akv;
            if (m0 + ar0 < n)      p0 = *(const float4*)(A + (size_t)(m0 + ar0) * D + kg);
            if (m0 + ar0 + 64 < n) p1 = *(const float4*)(A + (size_t)(m0 + ar0 + 64) * D + kg);
        }

        const float* Ahi = sA + (kt & 1) * 2 * ATILE;
        const float* Alo = Ahi + ATILE;

#pragma unroll
        for (int k8 = 0; k8 < BK; k8 += 8) {
            const int ar = (mw * 16 + g) * SRA + k8 + q;
            uint32_t ah[4], al[4];
            ah[0] = __float_as_uint(Ahi[ar]);
            ah[1] = __float_as_uint(Ahi[ar + 8 * SRA]);
            ah[2] = __float_as_uint(Ahi[ar + 4]);
            ah[3] = __float_as_uint(Ahi[ar + 8 * SRA + 4]);
            al[0] = __float_as_uint(Alo[ar]);
            al[1] = __float_as_uint(Alo[ar + 8 * SRA]);
            al[2] = __float_as_uint(Alo[ar + 4]);
            al[3] = __float_as_uint(Alo[ar + 8 * SRA + 4]);

            const int kcol = kt * BK + k8 + q;
#pragma unroll
            for (int tn = 0; tn < 8; tn++) {
                const int br = (nw * 64 + tn * 8 + g) * SRW + kcol;
                uint32_t bh[2], bl[2];
                bh[0] = __float_as_uint(sWhi[br]);
                bh[1] = __float_as_uint(sWhi[br + 4]);
                bl[0] = __float_as_uint(sWlo[br]);
                bl[1] = __float_as_uint(sWlo[br + 4]);
                mma_tf32(acc[tn], ah, bh);
                mma_tf32(acc[tn], ah, bl);
                mma_tf32(acc[tn], al, bh);
            }
        }

        if (kt < 3) {
            float* Dhi = sA + ((kt + 1) & 1) * 2 * ATILE;
            sts_split(Dhi, Dhi + ATILE, ar0 * SRA + akv, p0);
            sts_split(Dhi, Dhi + ATILE, (ar0 + 64) * SRA + akv, p1);
        }
        __syncthreads();
    }

    // ---- epilogue ----
    const int m_lo = m0 + mw * 16 + g;
    const int m_hi = m_lo + 8;
    float dot_lo = 0.f, dot_hi = 0.f;

#pragma unroll
    for (int tn = 0; tn < 8; tn++) {
        int c0 = nw * 64 + tn * 8 + 2 * q;
        float bx = __ldg(bias + c0), by = __ldg(bias + c0 + 1);
        float wx = __ldg(wa + c0),   wy = __ldg(wa + c0 + 1);

        float r0 = fmaxf(acc[tn][0] + bx, 0.f);
        float r1 = fmaxf(acc[tn][1] + by, 0.f);
        float r2 = fmaxf(acc[tn][2] + bx, 0.f);
        float r3 = fmaxf(acc[tn][3] + by, 0.f);
        dot_lo += r0 * wx + r1 * wy;
        dot_hi += r2 * wx + r3 * wy;

        if (m_lo < n) *(float2*)(out + (size_t)m_lo * D + c0) = make_float2(r0, r1);
        if (m_hi < n) *(float2*)(out + (size_t)m_hi * D + c0) = make_float2(r2, r3);
    }
#pragma unroll
    for (int off = 1; off < 4; off <<= 1) {
        dot_lo += __shfl_xor_sync(0xFFFFFFFFu, dot_lo, off);
        dot_hi += __shfl_xor_sync(0xFFFFFFFFu, dot_hi, off);
    }
    if (q == 0) {
        if (m_lo < n) atomicAdd(aout + m_lo, dot_lo);
        if (m_hi < n) atomicAdd(aout + m_hi, dot_hi);
    }
}

// ---------------------------------------------------------------------------
// init: detect edge dtype + zero counts + seed a1/a2 with attention bias.
// ---------------------------------------------------------------------------
__global__ void init_kernel(const unsigned int* __restrict__ ei,
                            const float* __restrict__ ba1,
                            const float* __restrict__ ba2, int n)
{
    if (blockIdx.x == 0 && threadIdx.x < 32) {
        int lane = threadIdx.x;
        unsigned v = ei[2 * lane + 1] | ei[2 * (lane + 32) + 1];
        unsigned all_zero = __all_sync(0xFFFFFFFFu, v == 0u);
        if (lane == 0) g_is64 = (int)all_zero;
    }
    int i = blockIdx.x * blockDim.x + threadIdx.x;
    if (i < n) {
        g_cnt[i] = 0;
        g_a1[i] = ba1[0];
        g_a2[i] = ba2[0];
    }
}

__device__ __forceinline__ int load_idx(const void* ei, size_t pos)
{
    if (g_is64) return (int)((const long long*)ei)[pos];
    return ((const int*)ei)[pos];
}

// ---------------------------------------------------------------------------
// CSR: histogram -> scan (smem-staged, coalesced) -> fill
// ---------------------------------------------------------------------------
__global__ __launch_bounds__(256) void hist_kernel(const void* __restrict__ ei, int e)
{
    int i = blockIdx.x * blockDim.x + threadIdx.x;
    if (i >= e) return;
    atomicAdd(&g_cnt[load_idx(ei, i)], 1);
}

#define SCAN_T 1024
__global__ __launch_bounds__(SCAN_T) void scan_kernel(int n)
{
    extern __shared__ int sc[];          // n counts + SCAN_T partial sums
    int* ssum = sc + n;
    int t = threadIdx.x;

    for (int i = t; i < n; i += SCAN_T) sc[i] = g_cnt[i];
    __syncthreads();

    int per = (n + SCAN_T - 1) / SCAN_T;
    int base = t * per;
    int s = 0;
    for (int i = 0; i < per; i++) {
        int idx = base + i;
        if (idx < n) s += sc[idx];
    }
    ssum[t] = s;
    __syncthreads();
    for (int off = 1; off < SCAN_T; off <<= 1) {
        int y = (t >= off) ? ssum[t - off] : 0;
        __syncthreads();
        if (t >= off) ssum[t] += y;
        __syncthreads();
    }
    int run = ssum[t] - s;   // exclusive prefix of this chunk
    for (int i = 0; i < per; i++) {
        int idx = base + i;
        if (idx < n) {
            int c = sc[idx];
            sc[idx] = run;
            run += c;
        }
    }
    __syncthreads();
    for (int i = t; i < n; i += SCAN_T) {
        int v = sc[i];
        g_rowptr[i] = v;
        g_cursor[i] = v;
    }
    if (t == SCAN_T - 1) g_rowptr[n] = run;
}

__global__ __launch_bounds__(256) void fill_kernel(const void* __restrict__ ei, int e)
{
    int i = blockIdx.x * blockDim.x + threadIdx.x;
    if (i >= e) return;
    int r = load_idx(ei, i);
    int c = load_idx(ei, (size_t)e + i);
    int pos = atomicAdd(&g_cursor[r], 1);
    g_csr_col[pos] = c;
}

// ---------------------------------------------------------------------------
// Gather: one warp per destination node, column prefetch 1 deep.
// ---------------------------------------------------------------------------
__global__ __launch_bounds__(256) void gather_kernel(float* __restrict__ out, int n)
{
    int w    = (blockIdx.x * blockDim.x + threadIdx.x) >> 5;
    int lane = threadIdx.x & 31;
    if (w >= n) return;

    float a1v = g_a1[w];

    float att = 1.f / (1.f + __expf(-(a1v + g_a2[w])));
    float4 fi4 = *(const float4*)(g_fi + (size_t)w * D + lane * 4);
    float4 fj4 = *(const float4*)(g_fj + (size_t)w * D + lane * 4);
    float4 acc;
    acc.x = fi4.x + att * fj4.x;
    acc.y = fi4.y + att * fj4.y;
    acc.z = fi4.z + att * fj4.z;
    acc.w = fi4.w + att * fj4.w;

    int s = g_rowptr[w];
    int t = g_rowptr[w + 1];
    int c_next = (s < t) ? __ldg(&g_csr_col[s]) : 0;
    for (int k = s; k < t; k++) {
        int c = c_next;
        if (k + 1 < t) c_next = __ldg(&g_csr_col[k + 1]);
        float a = 1.f / (1.f + __expf(-(a1v + __ldg(&g_a2[c]))));
        float4 v = *(const float4*)(g_fj + (size_t)c * D + lane * 4);
        acc.x += a * v.x;
        acc.y += a * v.y;
        acc.z += a * v.z;
        acc.w += a * v.w;
    }
    *(float4*)(out + (size_t)w * D + lane * 4) = acc;
}

// ---------------------------------------------------------------------------
extern "C" void kernel_launch(void* const* d_in, const int* in_sizes, int n_in,
                              void* d_out, int out_size)
{
    const float* feat = (const float*)d_in[0];
    const float* W1   = (const float*)d_in[1];
    const float* b1   = (const float*)d_in[2];
    const float* W2   = (const float*)d_in[3];
    const float* b2   = (const float*)d_in[4];
    const float* wa1  = (const float*)d_in[5];
    const float* ba1  = (const float*)d_in[6];
    const float* wa2  = (const float*)d_in[7];
    const float* ba2  = (const float*)d_in[8];
    const void*  ei   = d_in[9];

    int n = in_sizes[0] / D;
    int e = in_sizes[9] / 2;
    float* out = (float*)d_out;

    cudaFuncSetAttribute(gemm_tf32_kernel,
                         cudaFuncAttributeMaxDynamicSharedMemorySize, GEMM_SMEM);
    int scan_smem = (n + SCAN_T) * sizeof(int);
    cudaFuncSetAttribute(scan_kernel,
                         cudaFuncAttributeMaxDynamicSharedMemorySize, scan_smem);

    init_kernel<<<(n + 255) / 256, 256>>>((const unsigned int*)ei, ba1, ba2, n);

    dim3 grid_g((n + BM - 1) / BM, 2);
    gemm_tf32_kernel<<<grid_g, 512, GEMM_SMEM>>>(feat, W1, b1, W2, b2,
                                                 wa1, wa2, n);

    hist_kernel<<<(e + 255) / 256, 256>>>(ei, e);
    scan_kernel<<<1, SCAN_T, scan_smem>>>(n);
    fill_kernel<<<(e + 255) / 256, 256>>>(ei, e);

    gather_kernel<<<(n + 7) / 8, 256>>>(out, n);
}

// round 10
// speedup vs baseline: 2.2140x; 1.1433x over previous
#include <cuda_runtime.h>
#include <cstdint>

#define D 128
#define MAXN 50000
#define MAXE 800000

__device__ float g_fi[MAXN * D];
__device__ float g_fj[MAXN * D];
__device__ float g_a1[MAXN];
__device__ float g_a2[MAXN];
__device__ int   g_is64;
__device__ int   g_cnt[MAXN];
__device__ int   g_rowptr[MAXN + 1];
__device__ int   g_cursor[MAXN];
__device__ int   g_csr_col[MAXE];
__device__ int   g_part[512];        // per-block partial sums for the scan

// ---------------------------------------------------------------------------
// TF32 helpers: 3xTF32 split  x = hi + lo, hi = round_tf32(x)
// ---------------------------------------------------------------------------
__device__ __forceinline__ float f2tf32(float x)
{
    uint32_t r;
    asm("cvt.rna.tf32.f32 %0, %1;" : "=r"(r) : "f"(x));
    return __uint_as_float(r);
}

__device__ __forceinline__ void mma_tf32(float* c, const uint32_t* a,
                                         const uint32_t* b)
{
    asm volatile(
        "mma.sync.aligned.m16n8k8.row.col.f32.tf32.tf32.f32 "
        "{%0,%1,%2,%3}, {%4,%5,%6,%7}, {%8,%9}, {%0,%1,%2,%3};"
        : "+f"(c[0]), "+f"(c[1]), "+f"(c[2]), "+f"(c[3])
        : "r"(a[0]), "r"(a[1]), "r"(a[2]), "r"(a[3]), "r"(b[0]), "r"(b[1]));
}

__device__ __forceinline__ void sts_split(float* hi, float* lo, int off, float4 v)
{
    float4 h, l;
    h.x = f2tf32(v.x); l.x = v.x - h.x;
    h.y = f2tf32(v.y); l.y = v.y - h.y;
    h.z = f2tf32(v.z); l.z = v.z - h.z;
    h.w = f2tf32(v.w); l.w = v.w - h.w;
    *(float4*)(hi + off) = h;
    *(float4*)(lo + off) = l;
}

// ---------------------------------------------------------------------------
// Kernel 1: dual GEMM on tensor cores (3xTF32), 512 threads / block.
// (unchanged from round 4 — see its header comment)
// ---------------------------------------------------------------------------
#define BM 128
#define BK 32
#define SRA 36
#define SRW 132
#define ATILE (BM * SRA)
#define WTILE (BM * SRW)
#define GEMM_SMEM ((2 * WTILE + 4 * ATILE) * 4)   // 208896 bytes

__global__ __launch_bounds__(512) void gemm_tf32_kernel(
    const float* __restrict__ A,
    const float* __restrict__ W1, const float* __restrict__ b1,
    const float* __restrict__ W2, const float* __restrict__ b2,
    const float* __restrict__ wa1,
    const float* __restrict__ wa2,
    int n)
{
    extern __shared__ float sm[];
    float* sWhi = sm;
    float* sWlo = sm + WTILE;
    float* sA   = sm + 2 * WTILE;

    const float* W    = blockIdx.y ? W2  : W1;
    const float* bias = blockIdx.y ? b2  : b1;
    const float* wa   = blockIdx.y ? wa2 : wa1;
    float*       out  = blockIdx.y ? g_fj : g_fi;
    float*       aout = blockIdx.y ? g_a2 : g_a1;

    const int tid  = threadIdx.x;
    const int warp = tid >> 5;
    const int lane = tid & 31;
    const int q    = lane & 3;
    const int g    = lane >> 2;
    const int mw   = warp & 7;
    const int nw   = warp >> 3;
    const int m0   = blockIdx.x * BM;

#pragma unroll
    for (int i = 0; i < 8; i++) {
        int slot = tid + i * 512;
        int row  = slot >> 5;
        int kv   = (slot & 31) * 4;
        float4 wv = *(const float4*)(W + (size_t)row * D + kv);
        sts_split(sWhi, sWlo, row * SRW + kv, wv);
    }

    const int ar0 = tid >> 3;
    const int akv = (tid & 7) * 4;

    {
        float4 p0 = make_float4(0.f, 0.f, 0.f, 0.f);
        float4 p1 = make_float4(0.f, 0.f, 0.f, 0.f);
        if (m0 + ar0 < n)       p0 = *(const float4*)(A + (size_t)(m0 + ar0) * D + akv);
        if (m0 + ar0 + 64 < n)  p1 = *(const float4*)(A + (size_t)(m0 + ar0 + 64) * D + akv);
        sts_split(sA, sA + ATILE, ar0 * SRA + akv, p0);
        sts_split(sA, sA + ATILE, (ar0 + 64) * SRA + akv, p1);
    }
    __syncthreads();

    float acc[8][4];
#pragma unroll
    for (int t = 0; t < 8; t++)
#pragma unroll
        for (int j = 0; j < 4; j++) acc[t][j] = 0.f;

#pragma unroll
    for (int kt = 0; kt < 4; kt++) {
        float4 p0 = make_float4(0.f, 0.f, 0.f, 0.f);
        float4 p1 = make_float4(0.f, 0.f, 0.f, 0.f);
        if (kt < 3) {
            int kg = (kt + 1) * BK + akv;
            if (m0 + ar0 < n)      p0 = *(const float4*)(A + (size_t)(m0 + ar0) * D + kg);
            if (m0 + ar0 + 64 < n) p1 = *(const float4*)(A + (size_t)(m0 + ar0 + 64) * D + kg);
        }

        const float* Ahi = sA + (kt & 1) * 2 * ATILE;
        const float* Alo = Ahi + ATILE;

#pragma unroll
        for (int k8 = 0; k8 < BK; k8 += 8) {
            const int ar = (mw * 16 + g) * SRA + k8 + q;
            uint32_t ah[4], al[4];
            ah[0] = __float_as_uint(Ahi[ar]);
            ah[1] = __float_as_uint(Ahi[ar + 8 * SRA]);
            ah[2] = __float_as_uint(Ahi[ar + 4]);
            ah[3] = __float_as_uint(Ahi[ar + 8 * SRA + 4]);
            al[0] = __float_as_uint(Alo[ar]);
            al[1] = __float_as_uint(Alo[ar + 8 * SRA]);
            al[2] = __float_as_uint(Alo[ar + 4]);
            al[3] = __float_as_uint(Alo[ar + 8 * SRA + 4]);

            const int kcol = kt * BK + k8 + q;
#pragma unroll
            for (int tn = 0; tn < 8; tn++) {
                const int br = (nw * 64 + tn * 8 + g) * SRW + kcol;
                uint32_t bh[2], bl[2];
                bh[0] = __float_as_uint(sWhi[br]);
                bh[1] = __float_as_uint(sWhi[br + 4]);
                bl[0] = __float_as_uint(sWlo[br]);
                bl[1] = __float_as_uint(sWlo[br + 4]);
                mma_tf32(acc[tn], ah, bh);
                mma_tf32(acc[tn], ah, bl);
                mma_tf32(acc[tn], al, bh);
            }
        }

        if (kt < 3) {
            float* Dhi = sA + ((kt + 1) & 1) * 2 * ATILE;
            sts_split(Dhi, Dhi + ATILE, ar0 * SRA + akv, p0);
            sts_split(Dhi, Dhi + ATILE, (ar0 + 64) * SRA + akv, p1);
        }
        __syncthreads();
    }

    const int m_lo = m0 + mw * 16 + g;
    const int m_hi = m_lo + 8;
    float dot_lo = 0.f, dot_hi = 0.f;

#pragma unroll
    for (int tn = 0; tn < 8; tn++) {
        int c0 = nw * 64 + tn * 8 + 2 * q;
        float bx = __ldg(bias + c0), by = __ldg(bias + c0 + 1);
        float wx = __ldg(wa + c0),   wy = __ldg(wa + c0 + 1);

        float r0 = fmaxf(acc[tn][0] + bx, 0.f);
        float r1 = fmaxf(acc[tn][1] + by, 0.f);
        float r2 = fmaxf(acc[tn][2] + bx, 0.f);
        float r3 = fmaxf(acc[tn][3] + by, 0.f);
        dot_lo += r0 * wx + r1 * wy;
        dot_hi += r2 * wx + r3 * wy;

        if (m_lo < n) *(float2*)(out + (size_t)m_lo * D + c0) = make_float2(r0, r1);
        if (m_hi < n) *(float2*)(out + (size_t)m_hi * D + c0) = make_float2(r2, r3);
    }
#pragma unroll
    for (int off = 1; off < 4; off <<= 1) {
        dot_lo += __shfl_xor_sync(0xFFFFFFFFu, dot_lo, off);
        dot_hi += __shfl_xor_sync(0xFFFFFFFFu, dot_hi, off);
    }
    if (q == 0) {
        if (m_lo < n) atomicAdd(aout + m_lo, dot_lo);
        if (m_hi < n) atomicAdd(aout + m_hi, dot_hi);
    }
}

// ---------------------------------------------------------------------------
// init: detect edge dtype + zero counts + seed a1/a2 with attention bias.
// ---------------------------------------------------------------------------
__global__ void init_kernel(const unsigned int* __restrict__ ei,
                            const float* __restrict__ ba1,
                            const float* __restrict__ ba2, int n)
{
    if (blockIdx.x == 0 && threadIdx.x < 32) {
        int lane = threadIdx.x;
        unsigned v = ei[2 * lane + 1] | ei[2 * (lane + 32) + 1];
        unsigned all_zero = __all_sync(0xFFFFFFFFu, v == 0u);
        if (lane == 0) g_is64 = (int)all_zero;
    }
    int i = blockIdx.x * blockDim.x + threadIdx.x;
    if (i < n) {
        g_cnt[i] = 0;
        g_a1[i] = ba1[0];
        g_a2[i] = ba2[0];
    }
}

__device__ __forceinline__ int load_idx(const void* ei, size_t pos)
{
    if (g_is64) return (int)((const long long*)ei)[pos];
    return ((const int*)ei)[pos];
}

// ---------------------------------------------------------------------------
// CSR: histogram -> grid-wide 3-phase scan -> fill
// ---------------------------------------------------------------------------
__global__ __launch_bounds__(256) void hist_kernel(const void* __restrict__ ei, int e)
{
    int i = blockIdx.x * blockDim.x + threadIdx.x;
    if (i >= e) return;
    atomicAdd(&g_cnt[load_idx(ei, i)], 1);
}

// Phase A: per-block (256-element chunk) sums
__global__ __launch_bounds__(256) void scanA_kernel(int n)
{
    int i = blockIdx.x * 256 + threadIdx.x;
    int v = (i < n) ? g_cnt[i] : 0;
#pragma unroll
    for (int off = 16; off >= 1; off >>= 1)
        v += __shfl_down_sync(0xFFFFFFFFu, v, off);
    __shared__ int ws[8];
    if ((threadIdx.x & 31) == 0) ws[threadIdx.x >> 5] = v;
    __syncthreads();
    if (threadIdx.x < 8) {
        int s = ws[threadIdx.x];
#pragma unroll
        for (int off = 4; off >= 1; off >>= 1)
            s += __shfl_down_sync(0xFFu, s, off);
        if (threadIdx.x == 0) g_part[blockIdx.x] = s;
    }
}

// Phase B: single block scans the (<=512) partials into exclusive offsets
__global__ __launch_bounds__(512) void scanB_kernel(int nb, int n)
{
    __shared__ int sp[512];
    int t = threadIdx.x;
    int v = (t < nb) ? g_part[t] : 0;
    sp[t] = v;
    __syncthreads();
#pragma unroll
    for (int off = 1; off < 512; off <<= 1) {
        int y = (t >= off) ? sp[t - off] : 0;
        __syncthreads();
        sp[t] += y;
        __syncthreads();
    }
    if (t < nb) g_part[t] = sp[t] - v;          // exclusive prefix
    if (t == nb - 1) g_rowptr[n] = sp[t];       // total
}

// Phase C: per-block local exclusive scan + offset, write rowptr & cursor
__global__ __launch_bounds__(256) void scanC_kernel(int n)
{
    __shared__ int sc[256];
    __shared__ int ws[8];
    int i = blockIdx.x * 256 + threadIdx.x;
    int t = threadIdx.x;
    int lane = t & 31;
    int wid  = t >> 5;
    int v = (i < n) ? g_cnt[i] : 0;

    // warp inclusive scan
    int x = v;
#pragma unroll
    for (int off = 1; off < 32; off <<= 1) {
        int y = __shfl_up_sync(0xFFFFFFFFu, x, off);
        if (lane >= off) x += y;
    }
    if (lane == 31) ws[wid] = x;
    __syncthreads();
    if (t < 8) {
        int s = ws[t];
#pragma unroll
        for (int off = 1; off < 8; off <<= 1) {
            int y = __shfl_up_sync(0xFFu, s, off);
            if (t >= off) s += y;
        }
        ws[t] = s;
    }
    __syncthreads();
    int excl = x - v + (wid ? ws[wid - 1] : 0) + g_part[blockIdx.x];
    if (i < n) {
        g_rowptr[i] = excl;
        g_cursor[i] = excl;
    }
}

__global__ __launch_bounds__(256) void fill_kernel(const void* __restrict__ ei, int e)
{
    int i = blockIdx.x * blockDim.x + threadIdx.x;
    if (i >= e) return;
    int r = load_idx(ei, i);
    int c = load_idx(ei, (size_t)e + i);
    int pos = atomicAdd(&g_cursor[r], 1);
    g_csr_col[pos] = c;
}

// ---------------------------------------------------------------------------
// Gather: one warp per destination node; software-pipelined 1 iteration deep
// (next col + next a2 + next fj row in flight during current FMA).
// ---------------------------------------------------------------------------
__global__ __launch_bounds__(256) void gather_kernel(float* __restrict__ out, int n)
{
    int w    = (blockIdx.x * blockDim.x + threadIdx.x) >> 5;
    int lane = threadIdx.x & 31;
    if (w >= n) return;

    float a1v = g_a1[w];

    float att = 1.f / (1.f + __expf(-(a1v + g_a2[w])));
    float4 fi4 = *(const float4*)(g_fi + (size_t)w * D + lane * 4);
    float4 fj4 = *(const float4*)(g_fj + (size_t)w * D + lane * 4);
    float4 acc;
    acc.x = fi4.x + att * fj4.x;
    acc.y = fi4.y + att * fj4.y;
    acc.z = fi4.z + att * fj4.z;
    acc.w = fi4.w + att * fj4.w;

    int s = g_rowptr[w];
    int t = g_rowptr[w + 1];
    if (s < t) {
        int    c_cur  = __ldg(&g_csr_col[s]);
        float  a2_cur = __ldg(&g_a2[c_cur]);
        float4 v_cur  = *(const float4*)(g_fj + (size_t)c_cur * D + lane * 4);
        for (int k = s; k < t; k++) {
            int    c_nxt = 0;
            float  a2_nxt = 0.f;
            float4 v_nxt = make_float4(0.f, 0.f, 0.f, 0.f);
            if (k + 1 < t) {
                c_nxt  = __ldg(&g_csr_col[k + 1]);
                a2_nxt = __ldg(&g_a2[c_nxt]);
                v_nxt  = *(const float4*)(g_fj + (size_t)c_nxt * D + lane * 4);
            }
            float a = 1.f / (1.f + __expf(-(a1v + a2_cur)));
            acc.x += a * v_cur.x;
            acc.y += a * v_cur.y;
            acc.z += a * v_cur.z;
            acc.w += a * v_cur.w;
            c_cur = c_nxt; a2_cur = a2_nxt; v_cur = v_nxt;
        }
    }
    *(float4*)(out + (size_t)w * D + lane * 4) = acc;
}

// ---------------------------------------------------------------------------
extern "C" void kernel_launch(void* const* d_in, const int* in_sizes, int n_in,
                              void* d_out, int out_size)
{
    const float* feat = (const float*)d_in[0];
    const float* W1   = (const float*)d_in[1];
    const float* b1   = (const float*)d_in[2];
    const float* W2   = (const float*)d_in[3];
    const float* b2   = (const float*)d_in[4];
    const float* wa1  = (const float*)d_in[5];
    const float* ba1  = (const float*)d_in[6];
    const float* wa2  = (const float*)d_in[7];
    const float* ba2  = (const float*)d_in[8];
    const void*  ei   = d_in[9];

    int n = in_sizes[0] / D;
    int e = in_sizes[9] / 2;
    float* out = (float*)d_out;
    int nb = (n + 255) / 256;

    cudaFuncSetAttribute(gemm_tf32_kernel,
                         cudaFuncAttributeMaxDynamicSharedMemorySize, GEMM_SMEM);

    init_kernel<<<(n + 255) / 256, 256>>>((const unsigned int*)ei, ba1, ba2, n);

    dim3 grid_g((n + BM - 1) / BM, 2);
    gemm_tf32_kernel<<<grid_g, 512, GEMM_SMEM>>>(feat, W1, b1, W2, b2,
                                                 wa1, wa2, n);

    hist_kernel<<<(e + 255) / 256, 256>>>(ei, e);
    scanA_kernel<<<nb, 256>>>(n);
    scanB_kernel<<<1, 512>>>(nb, n);
    scanC_kernel<<<nb, 256>>>(n);
    fill_kernel<<<(e + 255) / 256, 256>>>(ei, e);

    gather_kernel<<<(n + 7) / 8, 256>>>(out, n);
}

// round 11
// speedup vs baseline: 2.2677x; 1.0243x over previous
#include <cuda_runtime.h>
#include <cstdint>

#define D 128
#define MAXN 50000
#define MAXE 800000

__device__ float g_fi[MAXN * D];
__device__ float g_fj[MAXN * D];
__device__ float g_a1[MAXN];   // pure dot (bias folded into gather)
__device__ float g_a2[MAXN];
__device__ int   g_is64;
__device__ int   g_cnt[MAXN];
__device__ int   g_rowptr[MAXN + 1];
__device__ int   g_cursor[MAXN];
__device__ int   g_csr_col[MAXE];
__device__ int   g_part[512];

// ---------------------------------------------------------------------------
// TF32 helpers: 3xTF32 split  x = hi + lo, hi = round_tf32(x)
// ---------------------------------------------------------------------------
__device__ __forceinline__ float f2tf32(float x)
{
    uint32_t r;
    asm("cvt.rna.tf32.f32 %0, %1;" : "=r"(r) : "f"(x));
    return __uint_as_float(r);
}

__device__ __forceinline__ void mma_tf32(float* c, const uint32_t* a,
                                         const uint32_t* b)
{
    asm volatile(
        "mma.sync.aligned.m16n8k8.row.col.f32.tf32.tf32.f32 "
        "{%0,%1,%2,%3}, {%4,%5,%6,%7}, {%8,%9}, {%0,%1,%2,%3};"
        : "+f"(c[0]), "+f"(c[1]), "+f"(c[2]), "+f"(c[3])
        : "r"(a[0]), "r"(a[1]), "r"(a[2]), "r"(a[3]), "r"(b[0]), "r"(b[1]));
}

__device__ __forceinline__ void sts_split(float* hi, float* lo, int off, float4 v)
{
    float4 h, l;
    h.x = f2tf32(v.x); l.x = v.x - h.x;
    h.y = f2tf32(v.y); l.y = v.y - h.y;
    h.z = f2tf32(v.z); l.z = v.z - h.z;
    h.w = f2tf32(v.w); l.w = v.w - h.w;
    *(float4*)(hi + off) = h;
    *(float4*)(lo + off) = l;
}

__device__ __forceinline__ int load_idx(const void* ei, size_t pos)
{
    if (g_is64) return (int)((const long long*)ei)[pos];
    return ((const int*)ei)[pos];
}

// ---------------------------------------------------------------------------
// Kernel 1: dual GEMM (3xTF32) + embedded edge histogram.
// Each block first histograms its share of edge rows (atomics overlap other
// blocks' tensor work), then runs the GEMM as in round 4.
// ---------------------------------------------------------------------------
#define BM 128
#define BK 32
#define SRA 36
#define SRW 132
#define ATILE (BM * SRA)
#define WTILE (BM * SRW)
#define GEMM_SMEM ((2 * WTILE + 4 * ATILE) * 4)   // 208896 bytes

__global__ __launch_bounds__(512) void gemm_tf32_kernel(
    const float* __restrict__ A,
    const float* __restrict__ W1, const float* __restrict__ b1,
    const float* __restrict__ W2, const float* __restrict__ b2,
    const float* __restrict__ wa1,
    const float* __restrict__ wa2,
    const void* __restrict__ ei, int e,
    int n)
{
    extern __shared__ float sm[];
    float* sWhi = sm;
    float* sWlo = sm + WTILE;
    float* sA   = sm + 2 * WTILE;

    const int tid  = threadIdx.x;

    // ---- embedded histogram: this block's share of edge rows ----
    {
        int nblk   = gridDim.x * gridDim.y;
        int bidlin = blockIdx.y * gridDim.x + blockIdx.x;
        int stride = nblk * 512;
        for (int idx = bidlin * 512 + tid; idx < e; idx += stride)
            atomicAdd(&g_cnt[load_idx(ei, idx)], 1);
    }

    const float* W    = blockIdx.y ? W2  : W1;
    const float* bias = blockIdx.y ? b2  : b1;
    const float* wa   = blockIdx.y ? wa2 : wa1;
    float*       out  = blockIdx.y ? g_fj : g_fi;
    float*       aout = blockIdx.y ? g_a2 : g_a1;

    const int warp = tid >> 5;
    const int lane = tid & 31;
    const int q    = lane & 3;
    const int g    = lane >> 2;
    const int mw   = warp & 7;
    const int nw   = warp >> 3;
    const int m0   = blockIdx.x * BM;

#pragma unroll
    for (int i = 0; i < 8; i++) {
        int slot = tid + i * 512;
        int row  = slot >> 5;
        int kv   = (slot & 31) * 4;
        float4 wv = *(const float4*)(W + (size_t)row * D + kv);
        sts_split(sWhi, sWlo, row * SRW + kv, wv);
    }

    const int ar0 = tid >> 3;
    const int akv = (tid & 7) * 4;

    {
        float4 p0 = make_float4(0.f, 0.f, 0.f, 0.f);
        float4 p1 = make_float4(0.f, 0.f, 0.f, 0.f);
        if (m0 + ar0 < n)       p0 = *(const float4*)(A + (size_t)(m0 + ar0) * D + akv);
        if (m0 + ar0 + 64 < n)  p1 = *(const float4*)(A + (size_t)(m0 + ar0 + 64) * D + akv);
        sts_split(sA, sA + ATILE, ar0 * SRA + akv, p0);
        sts_split(sA, sA + ATILE, (ar0 + 64) * SRA + akv, p1);
    }
    __syncthreads();

    float acc[8][4];
#pragma unroll
    for (int t = 0; t < 8; t++)
#pragma unroll
        for (int j = 0; j < 4; j++) acc[t][j] = 0.f;

#pragma unroll
    for (int kt = 0; kt < 4; kt++) {
        float4 p0 = make_float4(0.f, 0.f, 0.f, 0.f);
        float4 p1 = make_float4(0.f, 0.f, 0.f, 0.f);
        if (kt < 3) {
            int kg = (kt + 1) * BK + akv;
            if (m0 + ar0 < n)      p0 = *(const float4*)(A + (size_t)(m0 + ar0) * D + kg);
            if (m0 + ar0 + 64 < n) p1 = *(const float4*)(A + (size_t)(m0 + ar0 + 64) * D + kg);
        }

        const float* Ahi = sA + (kt & 1) * 2 * ATILE;
        const float* Alo = Ahi + ATILE;

#pragma unroll
        for (int k8 = 0; k8 < BK; k8 += 8) {
            const int ar = (mw * 16 + g) * SRA + k8 + q;
            uint32_t ah[4], al[4];
            ah[0] = __float_as_uint(Ahi[ar]);
            ah[1] = __float_as_uint(Ahi[ar + 8 * SRA]);
            ah[2] = __float_as_uint(Ahi[ar + 4]);
            ah[3] = __float_as_uint(Ahi[ar + 8 * SRA + 4]);
            al[0] = __float_as_uint(Alo[ar]);
            al[1] = __float_as_uint(Alo[ar + 8 * SRA]);
            al[2] = __float_as_uint(Alo[ar + 4]);
            al[3] = __float_as_uint(Alo[ar + 8 * SRA + 4]);

            const int kcol = kt * BK + k8 + q;
#pragma unroll
            for (int tn = 0; tn < 8; tn++) {
                const int br = (nw * 64 + tn * 8 + g) * SRW + kcol;
                uint32_t bh[2], bl[2];
                bh[0] = __float_as_uint(sWhi[br]);
                bh[1] = __float_as_uint(sWhi[br + 4]);
                bl[0] = __float_as_uint(sWlo[br]);
                bl[1] = __float_as_uint(sWlo[br + 4]);
                mma_tf32(acc[tn], ah, bh);
                mma_tf32(acc[tn], ah, bl);
                mma_tf32(acc[tn], al, bh);
            }
        }

        if (kt < 3) {
            float* Dhi = sA + ((kt + 1) & 1) * 2 * ATILE;
            sts_split(Dhi, Dhi + ATILE, ar0 * SRA + akv, p0);
            sts_split(Dhi, Dhi + ATILE, (ar0 + 64) * SRA + akv, p1);
        }
        __syncthreads();
    }

    const int m_lo = m0 + mw * 16 + g;
    const int m_hi = m_lo + 8;
    float dot_lo = 0.f, dot_hi = 0.f;

#pragma unroll
    for (int tn = 0; tn < 8; tn++) {
        int c0 = nw * 64 + tn * 8 + 2 * q;
        float bx = __ldg(bias + c0), by = __ldg(bias + c0 + 1);
        float wx = __ldg(wa + c0),   wy = __ldg(wa + c0 + 1);

        float r0 = fmaxf(acc[tn][0] + bx, 0.f);
        float r1 = fmaxf(acc[tn][1] + by, 0.f);
        float r2 = fmaxf(acc[tn][2] + bx, 0.f);
        float r3 = fmaxf(acc[tn][3] + by, 0.f);
        dot_lo += r0 * wx + r1 * wy;
        dot_hi += r2 * wx + r3 * wy;

        if (m_lo < n) *(float2*)(out + (size_t)m_lo * D + c0) = make_float2(r0, r1);
        if (m_hi < n) *(float2*)(out + (size_t)m_hi * D + c0) = make_float2(r2, r3);
    }
#pragma unroll
    for (int off = 1; off < 4; off <<= 1) {
        dot_lo += __shfl_xor_sync(0xFFFFFFFFu, dot_lo, off);
        dot_hi += __shfl_xor_sync(0xFFFFFFFFu, dot_hi, off);
    }
    if (q == 0) {
        if (m_lo < n) atomicAdd(aout + m_lo, dot_lo);
        if (m_hi < n) atomicAdd(aout + m_hi, dot_hi);
    }
}

// ---------------------------------------------------------------------------
// init: detect edge dtype + zero counts + zero a1/a2 (bias folded into gather)
// ---------------------------------------------------------------------------
__global__ void init_kernel(const unsigned int* __restrict__ ei, int n)
{
    if (blockIdx.x == 0 && threadIdx.x < 32) {
        int lane = threadIdx.x;
        unsigned v = ei[2 * lane + 1] | ei[2 * (lane + 32) + 1];
        unsigned all_zero = __all_sync(0xFFFFFFFFu, v == 0u);
        if (lane == 0) g_is64 = (int)all_zero;
    }
    int i = blockIdx.x * blockDim.x + threadIdx.x;
    if (i < n) {
        g_cnt[i] = 0;
        g_a1[i] = 0.f;
        g_a2[i] = 0.f;
    }
}

// ---------------------------------------------------------------------------
// Scan phase A: per-block (256-chunk) sums into g_part
// ---------------------------------------------------------------------------
__global__ __launch_bounds__(256) void scanA_kernel(int n)
{
    int i = blockIdx.x * 256 + threadIdx.x;
    int v = (i < n) ? g_cnt[i] : 0;
#pragma unroll
    for (int off = 16; off >= 1; off >>= 1)
        v += __shfl_down_sync(0xFFFFFFFFu, v, off);
    __shared__ int ws[8];
    if ((threadIdx.x & 31) == 0) ws[threadIdx.x >> 5] = v;
    __syncthreads();
    if (threadIdx.x < 8) {
        int s = ws[threadIdx.x];
#pragma unroll
        for (int off = 4; off >= 1; off >>= 1)
            s += __shfl_down_sync(0xFFu, s, off);
        if (threadIdx.x == 0) g_part[blockIdx.x] = s;
    }
}

// ---------------------------------------------------------------------------
// Scan phase C (B folded in): every block redundantly reduces g_part to get
// its exclusive offset + total, then local exclusive scan of its 256 chunk.
// ---------------------------------------------------------------------------
__global__ __launch_bounds__(256) void scanC_kernel(int n, int nb)
{
    __shared__ int ws[8];
    __shared__ int ws2[8];
    __shared__ int s_off, s_tot;
    int t = threadIdx.x;
    int lane = t & 31;
    int wid  = t >> 5;
    int bid  = blockIdx.x;

    // reduce partials: offset = sum_{j<bid} part[j]; total = sum all
    int po = 0, pt = 0;
    for (int j = t; j < nb; j += 256) {
        int v = g_part[j];
        if (j < bid) po += v;
        pt += v;
    }
#pragma unroll
    for (int off = 16; off >= 1; off >>= 1) {
        po += __shfl_down_sync(0xFFFFFFFFu, po, off);
        pt += __shfl_down_sync(0xFFFFFFFFu, pt, off);
    }
    if (lane == 0) { ws[wid] = po; ws2[wid] = pt; }
    __syncthreads();
    if (t < 8) {
        int a = ws[t], b = ws2[t];
#pragma unroll
        for (int off = 4; off >= 1; off >>= 1) {
            a += __shfl_down_sync(0xFFu, a, off);
            b += __shfl_down_sync(0xFFu, b, off);
        }
        if (t == 0) { s_off = a; s_tot = b; }
    }
    __syncthreads();

    int i = bid * 256 + t;
    int v = (i < n) ? g_cnt[i] : 0;

    // block-local inclusive scan
    int x = v;
#pragma unroll
    for (int off = 1; off < 32; off <<= 1) {
        int y = __shfl_up_sync(0xFFFFFFFFu, x, off);
        if (lane >= off) x += y;
    }
    if (lane == 31) ws[wid] = x;
    __syncthreads();
    if (t < 8) {
        int s = ws[t];
#pragma unroll
        for (int off = 1; off < 8; off <<= 1) {
            int y = __shfl_up_sync(0xFFu, s, off);
            if (t >= off) s += y;
        }
        ws[t] = s;
    }
    __syncthreads();
    int excl = x - v + (wid ? ws[wid - 1] : 0) + s_off;
    if (i < n) {
        g_rowptr[i] = excl;
        g_cursor[i] = excl;
    }
    if (bid == nb - 1 && t == 0) g_rowptr[n] = s_tot;
}

__global__ __launch_bounds__(256) void fill_kernel(const void* __restrict__ ei, int e)
{
    int i = blockIdx.x * blockDim.x + threadIdx.x;
    if (i >= e) return;
    int r = load_idx(ei, i);
    int c = load_idx(ei, (size_t)e + i);
    int pos = atomicAdd(&g_cursor[r], 1);
    g_csr_col[pos] = c;
}

// ---------------------------------------------------------------------------
// Gather: one warp per destination node; 2-wide unrolled inner loop.
// Attention bias (ba1+ba2) folded into the sigmoid argument here.
// ---------------------------------------------------------------------------
__global__ __launch_bounds__(256) void gather_kernel(
    const float* __restrict__ ba1, const float* __restrict__ ba2,
    float* __restrict__ out, int n)
{
    int w    = (blockIdx.x * blockDim.x + threadIdx.x) >> 5;
    int lane = threadIdx.x & 31;
    if (w >= n) return;

    float bsum = __ldg(ba1) + __ldg(ba2);
    float a1b  = g_a1[w] + bsum;

    float att = 1.f / (1.f + __expf(-(a1b + g_a2[w])));
    float4 fi4 = *(const float4*)(g_fi + (size_t)w * D + lane * 4);
    float4 fj4 = *(const float4*)(g_fj + (size_t)w * D + lane * 4);
    float4 acc;
    acc.x = fi4.x + att * fj4.x;
    acc.y = fi4.y + att * fj4.y;
    acc.z = fi4.z + att * fj4.z;
    acc.w = fi4.w + att * fj4.w;

    int s = g_rowptr[w];
    int t = g_rowptr[w + 1];
    int k = s;
    for (; k + 1 < t; k += 2) {
        int c0 = __ldg(&g_csr_col[k]);
        int c1 = __ldg(&g_csr_col[k + 1]);
        float x0 = __ldg(&g_a2[c0]);
        float x1 = __ldg(&g_a2[c1]);
        float4 v0 = *(const float4*)(g_fj + (size_t)c0 * D + lane * 4);
        float4 v1 = *(const float4*)(g_fj + (size_t)c1 * D + lane * 4);
        float e0 = 1.f / (1.f + __expf(-(a1b + x0)));
        float e1 = 1.f / (1.f + __expf(-(a1b + x1)));
        acc.x += e0 * v0.x + e1 * v1.x;
        acc.y += e0 * v0.y + e1 * v1.y;
        acc.z += e0 * v0.z + e1 * v1.z;
        acc.w += e0 * v0.w + e1 * v1.w;
    }
    if (k < t) {
        int c0 = __ldg(&g_csr_col[k]);
        float x0 = __ldg(&g_a2[c0]);
        float4 v0 = *(const float4*)(g_fj + (size_t)c0 * D + lane * 4);
        float e0 = 1.f / (1.f + __expf(-(a1b + x0)));
        acc.x += e0 * v0.x;
        acc.y += e0 * v0.y;
        acc.z += e0 * v0.z;
        acc.w += e0 * v0.w;
    }
    *(float4*)(out + (size_t)w * D + lane * 4) = acc;
}

// ---------------------------------------------------------------------------
extern "C" void kernel_launch(void* const* d_in, const int* in_sizes, int n_in,
                              void* d_out, int out_size)
{
    const float* feat = (const float*)d_in[0];
    const float* W1   = (const float*)d_in[1];
    const float* b1   = (const float*)d_in[2];
    const float* W2   = (const float*)d_in[3];
    const float* b2   = (const float*)d_in[4];
    const float* wa1  = (const float*)d_in[5];
    const float* ba1  = (const float*)d_in[6];
    const float* wa2  = (const float*)d_in[7];
    const float* ba2  = (const float*)d_in[8];
    const void*  ei   = d_in[9];

    int n = in_sizes[0] / D;
    int e = in_sizes[9] / 2;
    float* out = (float*)d_out;
    int nb = (n + 255) / 256;

    cudaFuncSetAttribute(gemm_tf32_kernel,
                         cudaFuncAttributeMaxDynamicSharedMemorySize, GEMM_SMEM);

    init_kernel<<<(n + 255) / 256, 256>>>((const unsigned int*)ei, n);

    dim3 grid_g((n + BM - 1) / BM, 2);
    gemm_tf32_kernel<<<grid_g, 512, GEMM_SMEM>>>(feat, W1, b1, W2, b2,
                                                 wa1, wa2, ei, e, n);

    scanA_kernel<<<nb, 256>>>(n);
    scanC_kernel<<<nb, 256>>>(n, nb);
    fill_kernel<<<(e + 255) / 256, 256>>>(ei, e);

    gather_kernel<<<(n + 7) / 8, 256>>>(ba1, ba2, out, n);
}

// round 12
// speedup vs baseline: 2.4737x; 1.0908x over previous
#include <cuda_runtime.h>
#include <cstdint>

#define D 128
#define MAXN 50000
#define MAXE 800000

__device__ float g_fi[MAXN * D];
__device__ float g_fj[MAXN * D];
__device__ float g_a1[MAXN];   // pure dot (bias folded into gather)
__device__ float g_a2[MAXN];
__device__ int   g_is64;
__device__ int   g_cnt[MAXN];
__device__ int   g_rowptr[MAXN + 1];
__device__ int   g_cursor[MAXN];
__device__ int   g_csr_col[MAXE];
__device__ int   g_part[512];

// ---------------------------------------------------------------------------
// TF32 helpers: 3xTF32 split  x = hi + lo, hi = round_tf32(x)
// ---------------------------------------------------------------------------
__device__ __forceinline__ float f2tf32(float x)
{
    uint32_t r;
    asm("cvt.rna.tf32.f32 %0, %1;" : "=r"(r) : "f"(x));
    return __uint_as_float(r);
}

__device__ __forceinline__ void mma_tf32(float* c, const uint32_t* a,
                                         const uint32_t* b)
{
    asm volatile(
        "mma.sync.aligned.m16n8k8.row.col.f32.tf32.tf32.f32 "
        "{%0,%1,%2,%3}, {%4,%5,%6,%7}, {%8,%9}, {%0,%1,%2,%3};"
        : "+f"(c[0]), "+f"(c[1]), "+f"(c[2]), "+f"(c[3])
        : "r"(a[0]), "r"(a[1]), "r"(a[2]), "r"(a[3]), "r"(b[0]), "r"(b[1]));
}

__device__ __forceinline__ void sts_split(float* hi, float* lo, int off, float4 v)
{
    float4 h, l;
    h.x = f2tf32(v.x); l.x = v.x - h.x;
    h.y = f2tf32(v.y); l.y = v.y - h.y;
    h.z = f2tf32(v.z); l.z = v.z - h.z;
    h.w = f2tf32(v.w); l.w = v.w - h.w;
    *(float4*)(hi + off) = h;
    *(float4*)(lo + off) = l;
}

__device__ __forceinline__ int load_idx(const void* ei, size_t pos)
{
    if (g_is64) return (int)((const long long*)ei)[pos];
    return ((const int*)ei)[pos];
}

// ---------------------------------------------------------------------------
// Kernel 1: dual GEMM on tensor cores (3xTF32), 512 threads / block.
// Whole W (hi/lo split) staged once; A double-buffered. Epilogue fuses
// bias+relu store and the attention-logit dot (atomicAdd into a1/a2).
// ---------------------------------------------------------------------------
#define BM 128
#define BK 32
#define SRA 36
#define SRW 132
#define ATILE (BM * SRA)
#define WTILE (BM * SRW)
#define GEMM_SMEM ((2 * WTILE + 4 * ATILE) * 4)   // 208896 bytes

__global__ __launch_bounds__(512) void gemm_tf32_kernel(
    const float* __restrict__ A,
    const float* __restrict__ W1, const float* __restrict__ b1,
    const float* __restrict__ W2, const float* __restrict__ b2,
    const float* __restrict__ wa1,
    const float* __restrict__ wa2,
    int n)
{
    extern __shared__ float sm[];
    float* sWhi = sm;
    float* sWlo = sm + WTILE;
    float* sA   = sm + 2 * WTILE;

    const float* W    = blockIdx.y ? W2  : W1;
    const float* bias = blockIdx.y ? b2  : b1;
    const float* wa   = blockIdx.y ? wa2 : wa1;
    float*       out  = blockIdx.y ? g_fj : g_fi;
    float*       aout = blockIdx.y ? g_a2 : g_a1;

    const int tid  = threadIdx.x;
    const int warp = tid >> 5;
    const int lane = tid & 31;
    const int q    = lane & 3;
    const int g    = lane >> 2;
    const int mw   = warp & 7;
    const int nw   = warp >> 3;
    const int m0   = blockIdx.x * BM;

#pragma unroll
    for (int i = 0; i < 8; i++) {
        int slot = tid + i * 512;
        int row  = slot >> 5;
        int kv   = (slot & 31) * 4;
        float4 wv = *(const float4*)(W + (size_t)row * D + kv);
        sts_split(sWhi, sWlo, row * SRW + kv, wv);
    }

    const int ar0 = tid >> 3;
    const int akv = (tid & 7) * 4;

    {
        float4 p0 = make_float4(0.f, 0.f, 0.f, 0.f);
        float4 p1 = make_float4(0.f, 0.f, 0.f, 0.f);
        if (m0 + ar0 < n)       p0 = *(const float4*)(A + (size_t)(m0 + ar0) * D + akv);
        if (m0 + ar0 + 64 < n)  p1 = *(const float4*)(A + (size_t)(m0 + ar0 + 64) * D + akv);
        sts_split(sA, sA + ATILE, ar0 * SRA + akv, p0);
        sts_split(sA, sA + ATILE, (ar0 + 64) * SRA + akv, p1);
    }
    __syncthreads();

    float acc[8][4];
#pragma unroll
    for (int t = 0; t < 8; t++)
#pragma unroll
        for (int j = 0; j < 4; j++) acc[t][j] = 0.f;

#pragma unroll
    for (int kt = 0; kt < 4; kt++) {
        float4 p0 = make_float4(0.f, 0.f, 0.f, 0.f);
        float4 p1 = make_float4(0.f, 0.f, 0.f, 0.f);
        if (kt < 3) {
            int kg = (kt + 1) * BK + akv;
            if (m0 + ar0 < n)      p0 = *(const float4*)(A + (size_t)(m0 + ar0) * D + kg);
            if (m0 + ar0 + 64 < n) p1 = *(const float4*)(A + (size_t)(m0 + ar0 + 64) * D + kg);
        }

        const float* Ahi = sA + (kt & 1) * 2 * ATILE;
        const float* Alo = Ahi + ATILE;

#pragma unroll
        for (int k8 = 0; k8 < BK; k8 += 8) {
            const int ar = (mw * 16 + g) * SRA + k8 + q;
            uint32_t ah[4], al[4];
            ah[0] = __float_as_uint(Ahi[ar]);
            ah[1] = __float_as_uint(Ahi[ar + 8 * SRA]);
            ah[2] = __float_as_uint(Ahi[ar + 4]);
            ah[3] = __float_as_uint(Ahi[ar + 8 * SRA + 4]);
            al[0] = __float_as_uint(Alo[ar]);
            al[1] = __float_as_uint(Alo[ar + 8 * SRA]);
            al[2] = __float_as_uint(Alo[ar + 4]);
            al[3] = __float_as_uint(Alo[ar + 8 * SRA + 4]);

            const int kcol = kt * BK + k8 + q;
#pragma unroll
            for (int tn = 0; tn < 8; tn++) {
                const int br = (nw * 64 + tn * 8 + g) * SRW + kcol;
                uint32_t bh[2], bl[2];
                bh[0] = __float_as_uint(sWhi[br]);
                bh[1] = __float_as_uint(sWhi[br + 4]);
                bl[0] = __float_as_uint(sWlo[br]);
                bl[1] = __float_as_uint(sWlo[br + 4]);
                mma_tf32(acc[tn], ah, bh);
                mma_tf32(acc[tn], ah, bl);
                mma_tf32(acc[tn], al, bh);
            }
        }

        if (kt < 3) {
            float* Dhi = sA + ((kt + 1) & 1) * 2 * ATILE;
            sts_split(Dhi, Dhi + ATILE, ar0 * SRA + akv, p0);
            sts_split(Dhi, Dhi + ATILE, (ar0 + 64) * SRA + akv, p1);
        }
        __syncthreads();
    }

    const int m_lo = m0 + mw * 16 + g;
    const int m_hi = m_lo + 8;
    float dot_lo = 0.f, dot_hi = 0.f;

#pragma unroll
    for (int tn = 0; tn < 8; tn++) {
        int c0 = nw * 64 + tn * 8 + 2 * q;
        float bx = __ldg(bias + c0), by = __ldg(bias + c0 + 1);
        float wx = __ldg(wa + c0),   wy = __ldg(wa + c0 + 1);

        float r0 = fmaxf(acc[tn][0] + bx, 0.f);
        float r1 = fmaxf(acc[tn][1] + by, 0.f);
        float r2 = fmaxf(acc[tn][2] + bx, 0.f);
        float r3 = fmaxf(acc[tn][3] + by, 0.f);
        dot_lo += r0 * wx + r1 * wy;
        dot_hi += r2 * wx + r3 * wy;

        if (m_lo < n) *(float2*)(out + (size_t)m_lo * D + c0) = make_float2(r0, r1);
        if (m_hi < n) *(float2*)(out + (size_t)m_hi * D + c0) = make_float2(r2, r3);
    }
#pragma unroll
    for (int off = 1; off < 4; off <<= 1) {
        dot_lo += __shfl_xor_sync(0xFFFFFFFFu, dot_lo, off);
        dot_hi += __shfl_xor_sync(0xFFFFFFFFu, dot_hi, off);
    }
    if (q == 0) {
        if (m_lo < n) atomicAdd(aout + m_lo, dot_lo);
        if (m_hi < n) atomicAdd(aout + m_hi, dot_hi);
    }
}

// ---------------------------------------------------------------------------
// init: detect edge dtype + zero counts + zero a1/a2
// ---------------------------------------------------------------------------
__global__ void init_kernel(const unsigned int* __restrict__ ei, int n)
{
    if (blockIdx.x == 0 && threadIdx.x < 32) {
        int lane = threadIdx.x;
        unsigned v = ei[2 * lane + 1] | ei[2 * (lane + 32) + 1];
        unsigned all_zero = __all_sync(0xFFFFFFFFu, v == 0u);
        if (lane == 0) g_is64 = (int)all_zero;
    }
    int i = blockIdx.x * blockDim.x + threadIdx.x;
    if (i < n) {
        g_cnt[i] = 0;
        g_a1[i] = 0.f;
        g_a2[i] = 0.f;
    }
}

// ---------------------------------------------------------------------------
// CSR chain (runs on the side stream, concurrent with the GEMM)
// ---------------------------------------------------------------------------
__global__ __launch_bounds__(256) void hist_kernel(const void* __restrict__ ei, int e)
{
    int i = blockIdx.x * blockDim.x + threadIdx.x;
    if (i >= e) return;
    atomicAdd(&g_cnt[load_idx(ei, i)], 1);
}

__global__ __launch_bounds__(256) void scanA_kernel(int n)
{
    int i = blockIdx.x * 256 + threadIdx.x;
    int v = (i < n) ? g_cnt[i] : 0;
#pragma unroll
    for (int off = 16; off >= 1; off >>= 1)
        v += __shfl_down_sync(0xFFFFFFFFu, v, off);
    __shared__ int ws[8];
    if ((threadIdx.x & 31) == 0) ws[threadIdx.x >> 5] = v;
    __syncthreads();
    if (threadIdx.x < 8) {
        int s = ws[threadIdx.x];
#pragma unroll
        for (int off = 4; off >= 1; off >>= 1)
            s += __shfl_down_sync(0xFFu, s, off);
        if (threadIdx.x == 0) g_part[blockIdx.x] = s;
    }
}

__global__ __launch_bounds__(256) void scanC_kernel(int n, int nb)
{
    __shared__ int ws[8];
    __shared__ int ws2[8];
    __shared__ int s_off, s_tot;
    int t = threadIdx.x;
    int lane = t & 31;
    int wid  = t >> 5;
    int bid  = blockIdx.x;

    int po = 0, pt = 0;
    for (int j = t; j < nb; j += 256) {
        int v = g_part[j];
        if (j < bid) po += v;
        pt += v;
    }
#pragma unroll
    for (int off = 16; off >= 1; off >>= 1) {
        po += __shfl_down_sync(0xFFFFFFFFu, po, off);
        pt += __shfl_down_sync(0xFFFFFFFFu, pt, off);
    }
    if (lane == 0) { ws[wid] = po; ws2[wid] = pt; }
    __syncthreads();
    if (t < 8) {
        int a = ws[t], b = ws2[t];
#pragma unroll
        for (int off = 4; off >= 1; off >>= 1) {
            a += __shfl_down_sync(0xFFu, a, off);
            b += __shfl_down_sync(0xFFu, b, off);
        }
        if (t == 0) { s_off = a; s_tot = b; }
    }
    __syncthreads();

    int i = bid * 256 + t;
    int v = (i < n) ? g_cnt[i] : 0;

    int x = v;
#pragma unroll
    for (int off = 1; off < 32; off <<= 1) {
        int y = __shfl_up_sync(0xFFFFFFFFu, x, off);
        if (lane >= off) x += y;
    }
    if (lane == 31) ws[wid] = x;
    __syncthreads();
    if (t < 8) {
        int s = ws[t];
#pragma unroll
        for (int off = 1; off < 8; off <<= 1) {
            int y = __shfl_up_sync(0xFFu, s, off);
            if (t >= off) s += y;
        }
        ws[t] = s;
    }
    __syncthreads();
    int excl = x - v + (wid ? ws[wid - 1] : 0) + s_off;
    if (i < n) {
        g_rowptr[i] = excl;
        g_cursor[i] = excl;
    }
    if (bid == nb - 1 && t == 0) g_rowptr[n] = s_tot;
}

__global__ __launch_bounds__(256) void fill_kernel(const void* __restrict__ ei, int e)
{
    int i = blockIdx.x * blockDim.x + threadIdx.x;
    if (i >= e) return;
    int r = load_idx(ei, i);
    int c = load_idx(ei, (size_t)e + i);
    int pos = atomicAdd(&g_cursor[r], 1);
    g_csr_col[pos] = c;
}

// ---------------------------------------------------------------------------
// Gather: one warp per destination node; 2-wide unrolled inner loop.
// ---------------------------------------------------------------------------
__global__ __launch_bounds__(256) void gather_kernel(
    const float* __restrict__ ba1, const float* __restrict__ ba2,
    float* __restrict__ out, int n)
{
    int w    = (blockIdx.x * blockDim.x + threadIdx.x) >> 5;
    int lane = threadIdx.x & 31;
    if (w >= n) return;

    float bsum = __ldg(ba1) + __ldg(ba2);
    float a1b  = g_a1[w] + bsum;

    float att = 1.f / (1.f + __expf(-(a1b + g_a2[w])));
    float4 fi4 = *(const float4*)(g_fi + (size_t)w * D + lane * 4);
    float4 fj4 = *(const float4*)(g_fj + (size_t)w * D + lane * 4);
    float4 acc;
    acc.x = fi4.x + att * fj4.x;
    acc.y = fi4.y + att * fj4.y;
    acc.z = fi4.z + att * fj4.z;
    acc.w = fi4.w + att * fj4.w;

    int s = g_rowptr[w];
    int t = g_rowptr[w + 1];
    int k = s;
    for (; k + 1 < t; k += 2) {
        int c0 = __ldg(&g_csr_col[k]);
        int c1 = __ldg(&g_csr_col[k + 1]);
        float x0 = __ldg(&g_a2[c0]);
        float x1 = __ldg(&g_a2[c1]);
        float4 v0 = *(const float4*)(g_fj + (size_t)c0 * D + lane * 4);
        float4 v1 = *(const float4*)(g_fj + (size_t)c1 * D + lane * 4);
        float e0 = 1.f / (1.f + __expf(-(a1b + x0)));
        float e1 = 1.f / (1.f + __expf(-(a1b + x1)));
        acc.x += e0 * v0.x + e1 * v1.x;
        acc.y += e0 * v0.y + e1 * v1.y;
        acc.z += e0 * v0.z + e1 * v1.z;
        acc.w += e0 * v0.w + e1 * v1.w;
    }
    if (k < t) {
        int c0 = __ldg(&g_csr_col[k]);
        float x0 = __ldg(&g_a2[c0]);
        float4 v0 = *(const float4*)(g_fj + (size_t)c0 * D + lane * 4);
        float e0 = 1.f / (1.f + __expf(-(a1b + x0)));
        acc.x += e0 * v0.x;
        acc.y += e0 * v0.y;
        acc.z += e0 * v0.z;
        acc.w += e0 * v0.w;
    }
    *(float4*)(out + (size_t)w * D + lane * 4) = acc;
}

// ---------------------------------------------------------------------------
// Launch: fork-join — CSR build (side stream) overlaps the GEMM (main stream).
//   main: init -> [fork] -> gemm ----------------> [join] -> gather
//   side:         [fork] -> hist -> scanA -> scanC -> fill -> [join]
// Streams/events created lazily on the first (uncaptured correctness) call;
// identical launch structure on every call.
// ---------------------------------------------------------------------------
extern "C" void kernel_launch(void* const* d_in, const int* in_sizes, int n_in,
                              void* d_out, int out_size)
{
    const float* feat = (const float*)d_in[0];
    const float* W1   = (const float*)d_in[1];
    const float* b1   = (const float*)d_in[2];
    const float* W2   = (const float*)d_in[3];
    const float* b2   = (const float*)d_in[4];
    const float* wa1  = (const float*)d_in[5];
    const float* ba1  = (const float*)d_in[6];
    const float* wa2  = (const float*)d_in[7];
    const float* ba2  = (const float*)d_in[8];
    const void*  ei   = d_in[9];

    int n = in_sizes[0] / D;
    int e = in_sizes[9] / 2;
    float* out = (float*)d_out;
    int nb = (n + 255) / 256;

    static cudaStream_t s_side = nullptr;
    static cudaEvent_t  ev_fork = nullptr, ev_join = nullptr;
    static bool s_ready = false;
    if (!s_ready) {
        cudaStreamCreateWithFlags(&s_side, cudaStreamNonBlocking);
        cudaEventCreateWithFlags(&ev_fork, cudaEventDisableTiming);
        cudaEventCreateWithFlags(&ev_join, cudaEventDisableTiming);
        cudaFuncSetAttribute(gemm_tf32_kernel,
                             cudaFuncAttributeMaxDynamicSharedMemorySize,
                             GEMM_SMEM);
        s_ready = true;
    }

    // main stream: init, then fork
    init_kernel<<<(n + 255) / 256, 256>>>((const unsigned int*)ei, n);
    cudaEventRecord(ev_fork, 0);

    // side stream: CSR build
    cudaStreamWaitEvent(s_side, ev_fork, 0);
    hist_kernel<<<(e + 255) / 256, 256, 0, s_side>>>(ei, e);
    scanA_kernel<<<nb, 256, 0, s_side>>>(n);
    scanC_kernel<<<nb, 256, 0, s_side>>>(n, nb);
    fill_kernel<<<(e + 255) / 256, 256, 0, s_side>>>(ei, e);
    cudaEventRecord(ev_join, s_side);

    // main stream: GEMM concurrent with the side chain
    dim3 grid_g((n + BM - 1) / BM, 2);
    gemm_tf32_kernel<<<grid_g, 512, GEMM_SMEM>>>(feat, W1, b1, W2, b2,
                                                 wa1, wa2, n);

    // join, then gather
    cudaStreamWaitEvent(0, ev_join, 0);
    gather_kernel<<<(n + 7) / 8, 256>>>(ba1, ba2, out, n);
}

// round 16
// speedup vs baseline: 2.9559x; 1.1949x over previous
#include <cuda_runtime.h>
#include <cuda_bf16.h>
#include <cstdint>

#define D 128
#define MAXN 50000
#define MAXE 800000

__device__ float g_fi[MAXN * D];
__device__ float g_fj[MAXN * D];
__device__ float g_a1[MAXN];
__device__ float g_a2[MAXN];
__device__ int   g_is64;
__device__ int   g_cnt[MAXN];
__device__ int   g_rowptr[MAXN + 1];
__device__ int   g_cursor[MAXN];
__device__ int   g_csr_col[MAXE];
__device__ int   g_part[512];

// ---------------------------------------------------------------------------
// bf16 2-term split helpers: x = hi + lo (both bf16); D += Ah*Bh + Ah*Bl + Al*Bh
// ---------------------------------------------------------------------------
__device__ __forceinline__ void mma_bf16(float* c, const uint32_t* a,
                                         const uint32_t* b)
{
    asm volatile(
        "mma.sync.aligned.m16n8k16.row.col.f32.bf16.bf16.f32 "
        "{%0,%1,%2,%3}, {%4,%5,%6,%7}, {%8,%9}, {%0,%1,%2,%3};"
        : "+f"(c[0]), "+f"(c[1]), "+f"(c[2]), "+f"(c[3])
        : "r"(a[0]), "r"(a[1]), "r"(a[2]), "r"(a[3]), "r"(b[0]), "r"(b[1]));
}

__device__ __forceinline__ unsigned short bf16_bits(__nv_bfloat16 h)
{
    return *(unsigned short*)&h;
}

// split float4 into hi/lo bf16 quads, store 8B each
__device__ __forceinline__ void split_store(__nv_bfloat16* hi, __nv_bfloat16* lo,
                                            int off, float4 v)
{
    __nv_bfloat16 h0 = __float2bfloat16(v.x);
    __nv_bfloat16 h1 = __float2bfloat16(v.y);
    __nv_bfloat16 h2 = __float2bfloat16(v.z);
    __nv_bfloat16 h3 = __float2bfloat16(v.w);
    __nv_bfloat16 l0 = __float2bfloat16(v.x - __bfloat162float(h0));
    __nv_bfloat16 l1 = __float2bfloat16(v.y - __bfloat162float(h1));
    __nv_bfloat16 l2 = __float2bfloat16(v.z - __bfloat162float(h2));
    __nv_bfloat16 l3 = __float2bfloat16(v.w - __bfloat162float(h3));
    *(ushort4*)(hi + off) = make_ushort4(bf16_bits(h0), bf16_bits(h1),
                                         bf16_bits(h2), bf16_bits(h3));
    *(ushort4*)(lo + off) = make_ushort4(bf16_bits(l0), bf16_bits(l1),
                                         bf16_bits(l2), bf16_bits(l3));
}

__device__ __forceinline__ int load_idx(const void* ei, size_t pos)
{
    if (g_is64) return (int)((const long long*)ei)[pos];
    return ((const int*)ei)[pos];
}

// ---------------------------------------------------------------------------
// Kernel 1: dual GEMM, bf16-split m16n8k16 tensor path, 512 threads/block.
// W (hi/lo bf16) staged once; A tiles (BK=32) double-buffered with register
// prefetch. Warp w = (mw=w&7, nw=w>>3) owns rows [mw*16,+16) x cols
// [nw*64,+64). Epilogue: bias+relu store + attention-logit dot reduced
// across nw-warps via smem (non-atomic single store, no zero-init needed).
// ---------------------------------------------------------------------------
#define BM 128
#define BK 32
#define SRA 40                       // halves: 80B row stride, bank-clean
#define SRW 136                      // halves: 272B row stride, bank-clean
#define ATILE (BM * SRA)             // 5120 halves
#define WTILE (BM * SRW)             // 17408 halves
#define GEMM_SMEM ((2 * WTILE + 4 * ATILE) * 2)   // 110592 bytes

__global__ __launch_bounds__(512) void gemm_bf16_kernel(
    const float* __restrict__ A,
    const float* __restrict__ W1, const float* __restrict__ b1,
    const float* __restrict__ W2, const float* __restrict__ b2,
    const float* __restrict__ wa1,
    const float* __restrict__ wa2,
    int n)
{
    extern __shared__ __nv_bfloat16 smh[];
    __nv_bfloat16* sWhi = smh;
    __nv_bfloat16* sWlo = smh + WTILE;
    __nv_bfloat16* sA   = smh + 2 * WTILE;   // [stage][hi/lo][ATILE]

    const float* W    = blockIdx.y ? W2  : W1;
    const float* bias = blockIdx.y ? b2  : b1;
    const float* wa   = blockIdx.y ? wa2 : wa1;
    float*       out  = blockIdx.y ? g_fj : g_fi;
    float*       aout = blockIdx.y ? g_a2 : g_a1;

    const int tid  = threadIdx.x;
    const int warp = tid >> 5;
    const int lane = tid & 31;
    const int q    = lane & 3;
    const int g    = lane >> 2;
    const int mw   = warp & 7;
    const int nw   = warp >> 3;
    const int m0   = blockIdx.x * BM;

    // ---- stage whole W as hi/lo bf16 ----
#pragma unroll
    for (int i = 0; i < 8; i++) {
        int slot = tid + i * 512;
        int row  = slot >> 5;
        int kv   = (slot & 31) * 4;
        float4 wv = *(const float4*)(W + (size_t)row * D + kv);
        split_store(sWhi, sWlo, row * SRW + kv, wv);
    }

    const int ar0 = tid >> 3;          // rows ar0, ar0+64
    const int akv = (tid & 7) * 4;

    {
        float4 p0 = make_float4(0.f, 0.f, 0.f, 0.f);
        float4 p1 = make_float4(0.f, 0.f, 0.f, 0.f);
        if (m0 + ar0 < n)       p0 = *(const float4*)(A + (size_t)(m0 + ar0) * D + akv);
        if (m0 + ar0 + 64 < n)  p1 = *(const float4*)(A + (size_t)(m0 + ar0 + 64) * D + akv);
        split_store(sA, sA + ATILE, ar0 * SRA + akv, p0);
        split_store(sA, sA + ATILE, (ar0 + 64) * SRA + akv, p1);
    }
    __syncthreads();

    float acc[8][4];
#pragma unroll
    for (int t = 0; t < 8; t++)
#pragma unroll
        for (int j = 0; j < 4; j++) acc[t][j] = 0.f;

#pragma unroll
    for (int kt = 0; kt < 4; kt++) {
        float4 p0 = make_float4(0.f, 0.f, 0.f, 0.f);
        float4 p1 = make_float4(0.f, 0.f, 0.f, 0.f);
        if (kt < 3) {
            int kg = (kt + 1) * BK + akv;
            if (m0 + ar0 < n)      p0 = *(const float4*)(A + (size_t)(m0 + ar0) * D + kg);
            if (m0 + ar0 + 64 < n) p1 = *(const float4*)(A + (size_t)(m0 + ar0 + 64) * D + kg);
        }

        const __nv_bfloat16* Ahi = sA + (kt & 1) * 2 * ATILE;
        const __nv_bfloat16* Alo = Ahi + ATILE;

#pragma unroll
        for (int ks = 0; ks < BK; ks += 16) {
            const int ab = (mw * 16 + g) * SRA + ks + 2 * q;
            uint32_t ah[4], al[4];
            ah[0] = *(const uint32_t*)(Ahi + ab);
            ah[1] = *(const uint32_t*)(Ahi + ab + 8 * SRA);
            ah[2] = *(const uint32_t*)(Ahi + ab + 8);
            ah[3] = *(const uint32_t*)(Ahi + ab + 8 * SRA + 8);
            al[0] = *(const uint32_t*)(Alo + ab);
            al[1] = *(const uint32_t*)(Alo + ab + 8 * SRA);
            al[2] = *(const uint32_t*)(Alo + ab + 8);
            al[3] = *(const uint32_t*)(Alo + ab + 8 * SRA + 8);

            const int kcol = kt * BK + ks + 2 * q;
#pragma unroll
            for (int tn = 0; tn < 8; tn++) {
                const int br = (nw * 64 + tn * 8 + g) * SRW + kcol;
                uint32_t bh[2], bl[2];
                bh[0] = *(const uint32_t*)(sWhi + br);
                bh[1] = *(const uint32_t*)(sWhi + br + 8);
                bl[0] = *(const uint32_t*)(sWlo + br);
                bl[1] = *(const uint32_t*)(sWlo + br + 8);
                mma_bf16(acc[tn], ah, bh);
                mma_bf16(acc[tn], ah, bl);
                mma_bf16(acc[tn], al, bh);
            }
        }

        if (kt < 3) {
            __nv_bfloat16* Dhi = sA + ((kt + 1) & 1) * 2 * ATILE;
            split_store(Dhi, Dhi + ATILE, ar0 * SRA + akv, p0);
            split_store(Dhi, Dhi + ATILE, (ar0 + 64) * SRA + akv, p1);
        }
        __syncthreads();
    }

    // ---- epilogue: bias+relu store, attention dot (smem cross-warp sum) ----
    const int m_lo = m0 + mw * 16 + g;
    const int m_hi = m_lo + 8;
    float dot_lo = 0.f, dot_hi = 0.f;

#pragma unroll
    for (int tn = 0; tn < 8; tn++) {
        int c0 = nw * 64 + tn * 8 + 2 * q;
        float bx = __ldg(bias + c0), by = __ldg(bias + c0 + 1);
        float wx = __ldg(wa + c0),   wy = __ldg(wa + c0 + 1);

        float r0 = fmaxf(acc[tn][0] + bx, 0.f);
        float r1 = fmaxf(acc[tn][1] + by, 0.f);
        float r2 = fmaxf(acc[tn][2] + bx, 0.f);
        float r3 = fmaxf(acc[tn][3] + by, 0.f);
        dot_lo += r0 * wx + r1 * wy;
        dot_hi += r2 * wx + r3 * wy;

        if (m_lo < n) *(float2*)(out + (size_t)m_lo * D + c0) = make_float2(r0, r1);
        if (m_hi < n) *(float2*)(out + (size_t)m_hi * D + c0) = make_float2(r2, r3);
    }
#pragma unroll
    for (int off = 1; off < 4; off <<= 1) {
        dot_lo += __shfl_xor_sync(0xFFFFFFFFu, dot_lo, off);
        dot_hi += __shfl_xor_sync(0xFFFFFFFFu, dot_hi, off);
    }

    float* sdot = (float*)smh;   // 256 floats, safe after final sync above
    if (q == 0) {
        sdot[(mw * 16 + g) * 2 + nw]     = dot_lo;
        sdot[(mw * 16 + g + 8) * 2 + nw] = dot_hi;
    }
    __syncthreads();
    if (q == 0 && nw == 0) {
        int r0 = (mw * 16 + g) * 2;
        int r1 = (mw * 16 + g + 8) * 2;
        if (m_lo < n) aout[m_lo] = sdot[r0] + sdot[r0 + 1];
        if (m_hi < n) aout[m_hi] = sdot[r1] + sdot[r1 + 1];
    }
}

// ---------------------------------------------------------------------------
// init (side stream): detect edge dtype + zero counts
// ---------------------------------------------------------------------------
__global__ void init_kernel(const unsigned int* __restrict__ ei, int n)
{
    if (blockIdx.x == 0 && threadIdx.x < 32) {
        int lane = threadIdx.x;
        unsigned v = ei[2 * lane + 1] | ei[2 * (lane + 32) + 1];
        unsigned all_zero = __all_sync(0xFFFFFFFFu, v == 0u);
        if (lane == 0) g_is64 = (int)all_zero;
    }
    int i = blockIdx.x * blockDim.x + threadIdx.x;
    if (i < n) g_cnt[i] = 0;
}

// ---------------------------------------------------------------------------
// CSR chain (side stream, concurrent with GEMM)
// ---------------------------------------------------------------------------
__global__ __launch_bounds__(256) void hist_kernel(const void* __restrict__ ei, int e)
{
    int i = blockIdx.x * blockDim.x + threadIdx.x;
    if (i >= e) return;
    atomicAdd(&g_cnt[load_idx(ei, i)], 1);
}

__global__ __launch_bounds__(256) void scanA_kernel(int n)
{
    int i = blockIdx.x * 256 + threadIdx.x;
    int v = (i < n) ? g_cnt[i] : 0;
#pragma unroll
    for (int off = 16; off >= 1; off >>= 1)
        v += __shfl_down_sync(0xFFFFFFFFu, v, off);
    __shared__ int ws[8];
    if ((threadIdx.x & 31) == 0) ws[threadIdx.x >> 5] = v;
    __syncthreads();
    if (threadIdx.x < 8) {
        int s = ws[threadIdx.x];
#pragma unroll
        for (int off = 4; off >= 1; off >>= 1)
            s += __shfl_down_sync(0xFFu, s, off);
        if (threadIdx.x == 0) g_part[blockIdx.x] = s;
    }
}

__global__ __launch_bounds__(256) void scanC_kernel(int n, int nb)
{
    __shared__ int ws[8];
    __shared__ int ws2[8];
    __shared__ int s_off, s_tot;
    int t = threadIdx.x;
    int lane = t & 31;
    int wid  = t >> 5;
    int bid  = blockIdx.x;

    int po = 0, pt = 0;
    for (int j = t; j < nb; j += 256) {
        int v = g_part[j];
        if (j < bid) po += v;
        pt += v;
    }
#pragma unroll
    for (int off = 16; off >= 1; off >>= 1) {
        po += __shfl_down_sync(0xFFFFFFFFu, po, off);
        pt += __shfl_down_sync(0xFFFFFFFFu, pt, off);
    }
    if (lane == 0) { ws[wid] = po; ws2[wid] = pt; }
    __syncthreads();
    if (t < 8) {
        int a = ws[t], b = ws2[t];
#pragma unroll
        for (int off = 4; off >= 1; off >>= 1) {
            a += __shfl_down_sync(0xFFu, a, off);
            b += __shfl_down_sync(0xFFu, b, off);
        }
        if (t == 0) { s_off = a; s_tot = b; }
    }
    __syncthreads();

    int i = bid * 256 + t;
    int v = (i < n) ? g_cnt[i] : 0;

    int x = v;
#pragma unroll
    for (int off = 1; off < 32; off <<= 1) {
        int y = __shfl_up_sync(0xFFFFFFFFu, x, off);
        if (lane >= off) x += y;
    }
    if (lane == 31) ws[wid] = x;
    __syncthreads();
    if (t < 8) {
        int s = ws[t];
#pragma unroll
        for (int off = 1; off < 8; off <<= 1) {
            int y = __shfl_up_sync(0xFFu, s, off);
            if (t >= off) s += y;
        }
        ws[t] = s;
    }
    __syncthreads();
    int excl = x - v + (wid ? ws[wid - 1] : 0) + s_off;
    if (i < n) {
        g_rowptr[i] = excl;
        g_cursor[i] = excl;
    }
    if (bid == nb - 1 && t == 0) g_rowptr[n] = s_tot;
}

__global__ __launch_bounds__(256) void fill_kernel(const void* __restrict__ ei, int e)
{
    int i = blockIdx.x * blockDim.x + threadIdx.x;
    if (i >= e) return;
    int r = load_idx(ei, i);
    int c = load_idx(ei, (size_t)e + i);
    int pos = atomicAdd(&g_cursor[r], 1);
    g_csr_col[pos] = c;
}

// ---------------------------------------------------------------------------
// Gather: one warp per destination node; 2-wide unrolled inner loop.
// ---------------------------------------------------------------------------
__global__ __launch_bounds__(256) void gather_kernel(
    const float* __restrict__ ba1, const float* __restrict__ ba2,
    float* __restrict__ out, int n)
{
    int w    = (blockIdx.x * blockDim.x + threadIdx.x) >> 5;
    int lane = threadIdx.x & 31;
    if (w >= n) return;

    float bsum = __ldg(ba1) + __ldg(ba2);
    float a1b  = g_a1[w] + bsum;

    float att = 1.f / (1.f + __expf(-(a1b + g_a2[w])));
    float4 fi4 = *(const float4*)(g_fi + (size_t)w * D + lane * 4);
    float4 fj4 = *(const float4*)(g_fj + (size_t)w * D + lane * 4);
    float4 acc;
    acc.x = fi4.x + att * fj4.x;
    acc.y = fi4.y + att * fj4.y;
    acc.z = fi4.z + att * fj4.z;
    acc.w = fi4.w + att * fj4.w;

    int s = g_rowptr[w];
    int t = g_rowptr[w + 1];
    int k = s;
    for (; k + 1 < t; k += 2) {
        int c0 = __ldg(&g_csr_col[k]);
        int c1 = __ldg(&g_csr_col[k + 1]);
        float x0 = __ldg(&g_a2[c0]);
        float x1 = __ldg(&g_a2[c1]);
        float4 v0 = *(const float4*)(g_fj + (size_t)c0 * D + lane * 4);
        float4 v1 = *(const float4*)(g_fj + (size_t)c1 * D + lane * 4);
        float e0 = 1.f / (1.f + __expf(-(a1b + x0)));
        float e1 = 1.f / (1.f + __expf(-(a1b + x1)));
        acc.x += e0 * v0.x + e1 * v1.x;
        acc.y += e0 * v0.y + e1 * v1.y;
        acc.z += e0 * v0.z + e1 * v1.z;
        acc.w += e0 * v0.w + e1 * v1.w;
    }
    if (k < t) {
        int c0 = __ldg(&g_csr_col[k]);
        float x0 = __ldg(&g_a2[c0]);
        float4 v0 = *(const float4*)(g_fj + (size_t)c0 * D + lane * 4);
        float e0 = 1.f / (1.f + __expf(-(a1b + x0)));
        acc.x += e0 * v0.x;
        acc.y += e0 * v0.y;
        acc.z += e0 * v0.z;
        acc.w += e0 * v0.w;
    }
    *(float4*)(out + (size_t)w * D + lane * 4) = acc;
}

// ---------------------------------------------------------------------------
// Launch: fork-join.
//   main: [fork] -> gemm -----------------------------> [join] -> gather
//   side: [fork] -> init -> hist -> scanA -> scanC -> fill -> [join]
// ---------------------------------------------------------------------------
extern "C" void kernel_launch(void* const* d_in, const int* in_sizes, int n_in,
                              void* d_out, int out_size)
{
    const float* feat = (const float*)d_in[0];
    const float* W1   = (const float*)d_in[1];
    const float* b1   = (const float*)d_in[2];
    const float* W2   = (const float*)d_in[3];
    const float* b2   = (const float*)d_in[4];
    const float* wa1  = (const float*)d_in[5];
    const float* ba1  = (const float*)d_in[6];
    const float* wa2  = (const float*)d_in[7];
    const float* ba2  = (const float*)d_in[8];
    const void*  ei   = d_in[9];

    int n = in_sizes[0] / D;
    int e = in_sizes[9] / 2;
    float* out = (float*)d_out;
    int nb = (n + 255) / 256;

    static cudaStream_t s_side = nullptr;
    static cudaEvent_t  ev_fork = nullptr, ev_join = nullptr;
    static bool s_ready = false;
    if (!s_ready) {
        cudaStreamCreateWithFlags(&s_side, cudaStreamNonBlocking);
        cudaEventCreateWithFlags(&ev_fork, cudaEventDisableTiming);
        cudaEventCreateWithFlags(&ev_join, cudaEventDisableTiming);
        cudaFuncSetAttribute(gemm_bf16_kernel,
                             cudaFuncAttributeMaxDynamicSharedMemorySize,
                             GEMM_SMEM);
        s_ready = true;
    }

    cudaEventRecord(ev_fork, 0);

    // side stream: CSR build
    cudaStreamWaitEvent(s_side, ev_fork, 0);
    init_kernel<<<(n + 255) / 256, 256, 0, s_side>>>((const unsigned int*)ei, n);
    hist_kernel<<<(e + 255) / 256, 256, 0, s_side>>>(ei, e);
    scanA_kernel<<<nb, 256, 0, s_side>>>(n);
    scanC_kernel<<<nb, 256, 0, s_side>>>(n, nb);
    fill_kernel<<<(e + 255) / 256, 256, 0, s_side>>>(ei, e);
    cudaEventRecord(ev_join, s_side);

    // main stream: GEMM concurrent with the side chain
    dim3 grid_g((n + BM - 1) / BM, 2);
    gemm_bf16_kernel<<<grid_g, 512, GEMM_SMEM>>>(feat, W1, b1, W2, b2,
                                                 wa1, wa2, n);

    cudaStreamWaitEvent(0, ev_join, 0);
    gather_kernel<<<(n + 7) / 8, 256>>>(ba1, ba2, out, n);
}